// round 14
// baseline (speedup 1.0000x reference)
#include <cuda_runtime.h>
#include <cuda_bf16.h>
#include <cuda_fp16.h>

// ---------------------------------------------------------------------------
// Retriever: out[e] = relu([q | h_e[h] | r_emb[r] | h_e[t]] @ W1 + b1) @ W2 + b2
//   R'     = rel_embs @ W1[270:398] + (q @ W1[0:128] + b1)    (500 x 128, fp16)
//   AB     = h_e @ [W1[128:270] | W1[398:540]]                (N x 256, fp16)
//            single-product fp16 mma.sync GEMM (fp32 accum); DDE columns
//            synthesized into SMEM inside the GEMM (128x128 tile, gridY=2).
//   out[e] = W2 . relu(AB[h,0:128] + AB[t,128:256] + R'[r]) + b2
// NOTES: harness PTX targets plain sm_100 -> tcgen05 unavailable; mma.sync only.
//        R9: DDE kernels are LSU/LTS-throughput bound; batching neutral.
//        R10: 128x256 GEMM tile regressed (mma-issue bound) -> 128x128 kept.
//        R12 LESSON: griddepsync waits only for the primary's TRIGGER (+flush
//        of pre-trigger writes). Early triggers without extra sync race.
//        R13: late triggers everywhere -> serial-equivalent, 149.6us.
//        R14: scat2 triggers EARLY so gemm prelaunches and overlaps scat2 with
//        k-tiles 0..7 (fill/prep data only); the tile-8 DDE dependency is
//        enforced by a device semaphore (threadFenceReduction pattern).
// ---------------------------------------------------------------------------

#define E_MAX 500000
#define N_MAX 100000
#define HE_W  144      // row pitch in fp16 for h_e / Wcat (142 used, 2 zero)

__device__ int    g_hh[E_MAX];
__device__ int    g_tt[E_MAX];
__device__ int    g_rr[E_MAX];
__device__ float4 g_f0[N_MAX];                         // fwd r1 sums + cnt_t in .z
__device__ float4 g_r0[N_MAX];                         // rev r1 sums + cnt_h in .z
__device__ float2 g_f1[N_MAX], g_f2[N_MAX];            // fwd rounds 2,3 sums
__device__ float2 g_r1[N_MAX], g_r2[N_MAX];            // rev rounds 2,3 sums
__device__ __half g_hef[(size_t)N_MAX * HE_W];         // h_e fp16 (cols 0..127)
__device__ __half g_wf[256 * HE_W];                    // Wcat fp16, [n][k]
__device__ uint4  g_ab[(size_t)N_MAX * 32];            // AB  [N,256] fp16
__device__ uint4  g_rp[512 * 16];                      // R' [NREL,128] fp16
__device__ unsigned g_sem;                             // scat2-complete semaphore

__device__ __forceinline__ unsigned packh2(float x, float y) {
    __half2 t = __floats2half2_rn(x, y);
    return *(unsigned*)&t;
}
__device__ __forceinline__ float2 h22f(unsigned u) {
    return __half22float2(*(__half2*)&u);
}
__device__ __forceinline__ void red2(float2* p, float x, float y) {
    asm volatile("red.global.add.v2.f32 [%0], {%1, %2};"
                 :: "l"(p), "f"(x), "f"(y) : "memory");
}
__device__ __forceinline__ void red4(float4* p, float x, float y, float z, float w) {
    asm volatile("red.global.add.v4.f32 [%0], {%1, %2, %3, %4};"
                 :: "l"(p), "f"(x), "f"(y), "f"(z), "f"(w) : "memory");
}

// ---------------- build h_e fp16 cols 0..127 + zero DDE state ----------------
__global__ void k_fill(const float* __restrict__ ent, const float* __restrict__ nont,
                       int Nn, int Ntext) {
    int i = blockIdx.x * 256 + threadIdx.x;
    if (i >= Nn * 32) return;
    int node = i >> 5, c4 = i & 31;
    const float* src = (node < Ntext) ? (ent + (size_t)node * 128 + c4 * 4)
                                      : (nont + c4 * 4);
    float4 v = *(const float4*)src;
    *(uint2*)(g_hef + (size_t)node * HE_W + c4 * 4) =
        make_uint2(packh2(v.x, v.y), packh2(v.z, v.w));
    if (c4 == 0) {   // piggyback: zero DDE accumulators
        g_f0[node] = make_float4(0.f, 0.f, 0.f, 0.f);
        g_r0[node] = make_float4(0.f, 0.f, 0.f, 0.f);
        g_f1[node] = make_float2(0.f, 0.f);
        g_f2[node] = make_float2(0.f, 0.f);
        g_r1[node] = make_float2(0.f, 0.f);
        g_r2[node] = make_float2(0.f, 0.f);
    }
}

// ------- ids -> int32 (+dtype detect) + DDE round 0; 2 edges per thread -------
// PDL primary: trigger at the END (after all writes). Also zeroes g_sem
// (ordered before scat2 via the late-trigger chain).
__global__ void k_convert(const void* ph, const void* pr, const void* pt,
                          const float* __restrict__ topic, int E) {
    if (blockIdx.x == 0 && threadIdx.x == 0) g_sem = 0;
    __shared__ int s64;
    if (threadIdx.x == 0) {
        // int64 vs int32: int64 view of int32 r-id buffer is >= 2^32 a.s.
        const long long* p = (const long long*)ph;
        const long long* qq = (const long long*)pr;
        int ok = 1;
        for (int i = 0; i < 8; i++) {
            long long v = p[i];  if (v < 0 || v >= 1000000) ok = 0;
            long long w = qq[i]; if (w < 0 || w >= 1000000) ok = 0;
        }
        s64 = ok;
    }
    __syncthreads();
    int base = (blockIdx.x * 256 + threadIdx.x) * 2;
    if (base < E) {
        int n2 = (base + 1 < E) ? 2 : 1;
        int h[2], r[2], t[2];
#pragma unroll
        for (int j = 0; j < 2; j++) {
            int e = base + ((j < n2) ? j : 0);
            if (s64) {
                h[j] = (int)((const long long*)ph)[e];
                r[j] = (int)((const long long*)pr)[e];
                t[j] = (int)((const long long*)pt)[e];
            } else {
                h[j] = ((const int*)ph)[e];
                r[j] = ((const int*)pr)[e];
                t[j] = ((const int*)pt)[e];
            }
        }
        const float2* tp2 = (const float2*)topic;
        float2 th0 = __ldg(tp2 + h[0]);
        float2 tt0 = __ldg(tp2 + t[0]);
        float2 th1 = __ldg(tp2 + h[1]);
        float2 tt1 = __ldg(tp2 + t[1]);
        g_hh[base] = h[0]; g_rr[base] = r[0]; g_tt[base] = t[0];
        red4(&g_f0[t[0]], th0.x, th0.y, 1.0f, 0.f);
        red4(&g_r0[h[0]], tt0.x, tt0.y, 1.0f, 0.f);
        if (n2 == 2) {
            g_hh[base + 1] = h[1]; g_rr[base + 1] = r[1]; g_tt[base + 1] = t[1];
            red4(&g_f0[t[1]], th1.x, th1.y, 1.0f, 0.f);
            red4(&g_r0[h[1]], tt1.x, tt1.y, 1.0f, 0.f);
        }
    }
    cudaTriggerProgrammaticLaunchCompletion();   // AFTER all work (R12 lesson)
}

// ------- DDE scatter round rd (1 or 2); 2 edges per thread --------------------
// rd==1: late trigger (scat2's griddepsync needs complete round-1 sums).
// rd==2: EARLY trigger (gemm k0..7 don't need DDE data); completion is
//        signalled via g_sem with the canonical fence/add pattern.
__global__ void k_scat(int rd, int E) {
    cudaGridDependencySynchronize();
    if (rd == 2) cudaTriggerProgrammaticLaunchCompletion();   // arm gemm prelaunch
    int base = (blockIdx.x * 256 + threadIdx.x) * 2;
    if (base < E) {
        int n2 = (base + 1 < E) ? 2 : 1;
        int e1 = (n2 == 2) ? base + 1 : base;
        int h0 = g_hh[base], t0 = g_tt[base];
        int h1 = g_hh[e1],   t1 = g_tt[e1];
        if (rd == 1) {
            float4 f0h0 = __ldg(&g_f0[h0]);
            float4 r0t0 = __ldg(&g_r0[t0]);
            float4 f0h1 = __ldg(&g_f0[h1]);
            float4 r0t1 = __ldg(&g_r0[t1]);
            float ia = 1.0f / fmaxf(f0h0.z, 1.0f);
            float ib = 1.0f / fmaxf(r0t0.z, 1.0f);
            float ic = 1.0f / fmaxf(f0h1.z, 1.0f);
            float id = 1.0f / fmaxf(r0t1.z, 1.0f);
            red2(&g_f1[t0], f0h0.x * ia, f0h0.y * ia);
            red2(&g_r1[h0], r0t0.x * ib, r0t0.y * ib);
            if (n2 == 2) {
                red2(&g_f1[t1], f0h1.x * ic, f0h1.y * ic);
                red2(&g_r1[h1], r0t1.x * id, r0t1.y * id);
            }
        } else {
            const float* cb = (const float*)g_f0;
            const float* ch = (const float*)g_r0;
            float ca0 = __ldg(cb + 4 * (size_t)h0 + 2);
            float cb0 = __ldg(ch + 4 * (size_t)t0 + 2);
            float ca1 = __ldg(cb + 4 * (size_t)h1 + 2);
            float cb1 = __ldg(ch + 4 * (size_t)t1 + 2);
            float2 f1h0 = __ldg(&g_f1[h0]);
            float2 r1t0 = __ldg(&g_r1[t0]);
            float2 f1h1 = __ldg(&g_f1[h1]);
            float2 r1t1 = __ldg(&g_r1[t1]);
            float ia = 1.0f / fmaxf(ca0, 1.0f);
            float ib = 1.0f / fmaxf(cb0, 1.0f);
            float ic = 1.0f / fmaxf(ca1, 1.0f);
            float id = 1.0f / fmaxf(cb1, 1.0f);
            red2(&g_f2[t0], f1h0.x * ia, f1h0.y * ia);
            red2(&g_r2[h0], r1t0.x * ib, r1t0.y * ib);
            if (n2 == 2) {
                red2(&g_f2[t1], f1h1.x * ic, f1h1.y * ic);
                red2(&g_r2[h1], r1t1.x * id, r1t1.y * id);
            }
        }
    }
    if (rd == 2) {
        // signal completion: make this block's reds visible, then count up
        __threadfence();
        __syncthreads();
        if (threadIdx.x == 0) atomicAdd(&g_sem, 1u);
    } else {
        cudaTriggerProgrammaticLaunchCompletion();   // late trigger (rd==1)
    }
}

// ------- prep: Wcat fp16 [n][k] | R' = rel@W1_r + (q@W1_q + b1), fp16 ----------
__global__ void k_prep(const float* __restrict__ W1, const float* __restrict__ rel,
                       const float* __restrict__ q, const float* __restrict__ b1,
                       int NREL) {
    int bid = blockIdx.x;
    int tid = threadIdx.x;
    if (bid < 144) {                       // Wcat: 256 elements of the [n][k] array
        int idx = bid * 256 + tid;
        int n = idx / 144, k = idx % 144;
        float v = 0.f;
        if (k < 142) v = (n < 128) ? W1[(128 + k) * 128 + n]
                                   : W1[(398 + k) * 128 + (n - 128)];
        g_wf[idx] = __float2half(v);
    } else {                               // two relations per block
        __shared__ float rs[256];
        __shared__ float qs[128];
        int r = (bid - 144) * 2 + (tid >> 7);
        int j = tid & 127;
        int base = tid & ~127;
        if (tid < 128) qs[tid] = q[tid];
        rs[tid] = (r < NREL) ? rel[(size_t)r * 128 + j] : 0.f;
        __syncthreads();
        if (r < NREL) {
            float accc = b1[j];
#pragma unroll 8
            for (int k = 0; k < 128; k++) accc += qs[k] * __ldg(&W1[k * 128 + j]);
            float accr = 0.f;
#pragma unroll 8
            for (int k = 0; k < 128; k++) accr += rs[base + k] * __ldg(&W1[(270 + k) * 128 + j]);
            ((__half*)g_rp)[(size_t)r * 128 + j] = __float2half(accc + accr);
        }
    }
}

// ---------------------------------------------------------------------------
// GEMM: AB[N,256] = h_e[N,144] @ Wcat[144,256], single-product fp16 mma.sync,
// fp32 accum. Block 128x128 (gridY = n-half), 8 warps (2x4), warp tile 64x32,
// BK=16, cp.async double-buffered. Prelaunches on scat2's early trigger and
// runs k-tiles 0..7 (fill/prep data only) concurrent with scat2; before the
// tile-8 DDE synthesis it waits on g_sem == nblk (all scat2 blocks done).
// Trigger at the very END (after epilogue stores) so k_edge sees complete AB.
// ---------------------------------------------------------------------------
#define APITCH 24   // smem row pitch in fp16 (48B -> conflict-free ldmatrix)
#define R_EL   (128 * APITCH)   // elements per region (3072)

__device__ __forceinline__ void ldsm4(unsigned* r, unsigned a) {
    asm volatile("ldmatrix.sync.aligned.m8n8.x4.shared.b16 {%0,%1,%2,%3}, [%4];"
                 : "=r"(r[0]), "=r"(r[1]), "=r"(r[2]), "=r"(r[3]) : "r"(a));
}
__device__ __forceinline__ void mma_f16(float* d, const unsigned* a, unsigned b0, unsigned b1) {
    asm volatile("mma.sync.aligned.m16n8k16.row.col.f32.f16.f16.f32 "
                 "{%0,%1,%2,%3}, {%4,%5,%6,%7}, {%8,%9}, {%0,%1,%2,%3};"
                 : "+f"(d[0]), "+f"(d[1]), "+f"(d[2]), "+f"(d[3])
                 : "r"(a[0]), "r"(a[1]), "r"(a[2]), "r"(a[3]), "r"(b0), "r"(b1));
}
__device__ __forceinline__ void cp16(unsigned dst, const void* src) {
    asm volatile("cp.async.ca.shared.global [%0], [%1], 16;" :: "r"(dst), "l"(src));
}

__global__ __launch_bounds__(256) void k_gemm(const float* __restrict__ topic,
                                              int Nn, unsigned nblk) {
    // smem regions (fp16 elements): Abuf0 [0,R) Abuf1 [R,2R) Bbuf0 [2R,3R) Bbuf1 [3R,4R)
    __shared__ __align__(16) __half sm[4 * R_EL];     // 24 KB
    unsigned smb = (unsigned)__cvta_generic_to_shared(sm);
    int tid = threadIdx.x;
    int m0 = blockIdx.x * 128, n0 = blockIdx.y * 128;
    int wid = tid >> 5, lane = tid & 31;
    int wm = (wid >> 2) * 64, wn = (wid & 3) * 32;

    // staging: slot 0 = A, slot 1 = B; per tile each thread copies one 16B unit.
    int row = tid >> 1, half = tid & 1;                // 128 rows x 2 halves
    const __half* gbase[2];
    unsigned dstoff[2];                                // bytes, excluding buf
    {
        int gr = m0 + row; if (gr >= Nn) gr = Nn - 1;
        gbase[0] = g_hef + (size_t)gr * HE_W + half * 8;
        gbase[1] = g_wf + (size_t)(n0 + row) * HE_W + half * 8;
        dstoff[0] = (unsigned)(row * APITCH + half * 8) * 2;
        dstoff[1] = (unsigned)(2 * R_EL + row * APITCH + half * 8) * 2;
    }
    const unsigned bufstride = R_EL * 2;               // bytes between buf0/buf1

    float acc[4][4][4];
#pragma unroll
    for (int i = 0; i < 4; i++)
#pragma unroll
        for (int j = 0; j < 4; j++)
#pragma unroll
            for (int k = 0; k < 4; k++) acc[i][j][k] = 0.f;

    int ldrow = lane & 15, ldk = (lane >> 4) * 8;

    // ---- prologue: stage tile 0 into buf 0 ----
    cp16(smb + dstoff[0], gbase[0]);
    cp16(smb + dstoff[1], gbase[1]);
    asm volatile("cp.async.commit_group;");

    for (int it = 0; it <= 8; ++it) {
        int buf = it & 1;
        asm volatile("cp.async.wait_group 0;");
        __syncthreads();

        if (it < 8) {
            unsigned bofs = (buf ^ 1) * bufstride;
            if (it + 1 < 8) {
                cp16(smb + bofs + dstoff[0], gbase[0] + (it + 1) * 16);
                cp16(smb + bofs + dstoff[1], gbase[1] + (it + 1) * 16);
            } else {
                // tile 8 needs scat2's DDE output: wait on the semaphore
                // (all scat2 blocks fenced + counted), NOT griddepsync.
                if (tid == 0) {
                    while (*(volatile unsigned*)&g_sem < nblk) __nanosleep(64);
                    __threadfence();
                }
                __syncthreads();
                // B via cp.async (Wcat cols 128..143), A synthesized
                cp16(smb + bofs + dstoff[1], gbase[1] + 8 * 16);
                int i = m0 + row; if (i >= Nn) i = Nn - 1;
                float v[8];
                if (half == 0) {  // cols 128..135: topic, fwd rounds 1..3
                    float2 tp = __ldg(((const float2*)topic) + i);
                    float4 f0 = g_f0[i];
                    float2 f1 = g_f1[i], f2 = g_f2[i];
                    float ict = 1.0f / fmaxf(f0.z, 1.0f);
                    v[0] = tp.x;       v[1] = tp.y;
                    v[2] = f0.x * ict; v[3] = f0.y * ict;
                    v[4] = f1.x * ict; v[5] = f1.y * ict;
                    v[6] = f2.x * ict; v[7] = f2.y * ict;
                } else {          // cols 136..143: rev rounds 1..3, pad
                    float4 r0 = g_r0[i];
                    float2 r1 = g_r1[i], r2 = g_r2[i];
                    float ich = 1.0f / fmaxf(r0.z, 1.0f);
                    v[0] = r0.x * ich; v[1] = r0.y * ich;
                    v[2] = r1.x * ich; v[3] = r1.y * ich;
                    v[4] = r2.x * ich; v[5] = r2.y * ich;
                    v[6] = 0.f;        v[7] = 0.f;
                }
                *(uint4*)((char*)sm + bofs + dstoff[0]) =
                    make_uint4(packh2(v[0], v[1]), packh2(v[2], v[3]),
                               packh2(v[4], v[5]), packh2(v[6], v[7]));
            }
            asm volatile("cp.async.commit_group;");
        }

        // ---- fragments from buf ----
        unsigned aoff = buf * bufstride;
        unsigned Af[4][4], Bf[2][4];
#pragma unroll
        for (int mf = 0; mf < 4; mf++) {
            unsigned r = (wm + mf * 16 + ldrow) * APITCH + ldk;
            ldsm4(Af[mf], smb + aoff + r * 2);
        }
#pragma unroll
        for (int nh = 0; nh < 2; nh++) {
            unsigned r = (wn + nh * 16 + ldrow) * APITCH + ldk;
            ldsm4(Bf[nh], smb + 2 * R_EL * 2 + aoff + r * 2);
        }
#pragma unroll
        for (int mf = 0; mf < 4; mf++)
#pragma unroll
            for (int nf = 0; nf < 4; nf++) {
                int nh = nf >> 1, sel = nf & 1;
                mma_f16(acc[mf][nf], Af[mf], Bf[nh][sel], Bf[nh][sel + 2]);
            }
        if (it < 8) __syncthreads();
    }

    // ---- epilogue: fp32 acc -> fp16 AB ----
    int g = lane >> 2, tg = lane & 3;
    unsigned* outw = (unsigned*)g_ab;
#pragma unroll
    for (int mf = 0; mf < 4; mf++)
#pragma unroll
        for (int nf = 0; nf < 4; nf++) {
            int col = n0 + wn + nf * 8 + 2 * tg;
            int r0 = m0 + wm + mf * 16 + g;
            if (r0 < Nn)
                outw[(size_t)r0 * 128 + (col >> 1)] = packh2(acc[mf][nf][0], acc[mf][nf][1]);
            int r1 = r0 + 8;
            if (r1 < Nn)
                outw[(size_t)r1 * 128 + (col >> 1)] = packh2(acc[mf][nf][2], acc[mf][nf][3]);
        }
    cudaTriggerProgrammaticLaunchCompletion();   // AFTER epilogue stores
}

// -------- edge stage: 4 edges per 16-lane group, 12 batched uint4 gathers -----
// PDL secondary of gemm: ids / R' / W2 (complete before gemm even launched)
// are loaded BEFORE griddepsync, overlapping gemm's drain; AB gathers after.
__device__ __forceinline__ float edge_dot(uint4 ua, uint4 ub, uint4 ur,
                                          float4 w0, float4 w1) {
    float2 a0 = h22f(ua.x), a1 = h22f(ua.y), a2 = h22f(ua.z), a3 = h22f(ua.w);
    float2 b0 = h22f(ub.x), b1 = h22f(ub.y), b2 = h22f(ub.z), b3 = h22f(ub.w);
    float2 c0 = h22f(ur.x), c1 = h22f(ur.y), c2 = h22f(ur.z), c3 = h22f(ur.w);
    return fmaxf(a0.x + b0.x + c0.x, 0.f) * w0.x
         + fmaxf(a0.y + b0.y + c0.y, 0.f) * w0.y
         + fmaxf(a1.x + b1.x + c1.x, 0.f) * w0.z
         + fmaxf(a1.y + b1.y + c1.y, 0.f) * w0.w
         + fmaxf(a2.x + b2.x + c2.x, 0.f) * w1.x
         + fmaxf(a2.y + b2.y + c2.y, 0.f) * w1.y
         + fmaxf(a3.x + b3.x + c3.x, 0.f) * w1.z
         + fmaxf(a3.y + b3.y + c3.y, 0.f) * w1.w;
}

__global__ __launch_bounds__(256) void k_edge(float* __restrict__ out,
                                              const float4* __restrict__ w2,
                                              const float* __restrict__ b2, int E) {
    int gt = blockIdx.x * 256 + threadIdx.x;
    int quad = gt >> 4, sub = gt & 15;
    int eb = quad * 4;
    if (eb >= E) { cudaGridDependencySynchronize(); return; }
    int e[4];
    bool v[4];
#pragma unroll
    for (int j = 0; j < 4; j++) {
        v[j] = (eb + j < E);
        e[j] = v[j] ? eb + j : E - 1;
    }
    int hh[4], tt[4], rr[4];
#pragma unroll
    for (int j = 0; j < 4; j++) {
        hh[j] = g_hh[e[j]]; tt[j] = g_tt[e[j]]; rr[j] = g_rr[e[j]];
    }
    // pre-sync: R' gathers + W2 (complete before gemm launched)
    uint4 ur[4];
#pragma unroll
    for (int j = 0; j < 4; j++) ur[j] = __ldg(&g_rp[(size_t)rr[j] * 16 + sub]);
    float4 w0 = __ldg(&w2[2 * sub]);
    float4 w1 = __ldg(&w2[2 * sub + 1]);

    cudaGridDependencySynchronize();   // AB (gemm output) ready after this

    uint4 ua[4], ub[4];
#pragma unroll
    for (int j = 0; j < 4; j++) ua[j] = __ldg(&g_ab[(size_t)hh[j] * 32 + sub]);
#pragma unroll
    for (int j = 0; j < 4; j++) ub[j] = __ldg(&g_ab[(size_t)tt[j] * 32 + 16 + sub]);

    float s[4];
#pragma unroll
    for (int j = 0; j < 4; j++) s[j] = edge_dot(ua[j], ub[j], ur[j], w0, w1);
#pragma unroll
    for (int m = 8; m >= 1; m >>= 1) {
#pragma unroll
        for (int j = 0; j < 4; j++) s[j] += __shfl_xor_sync(0xffffffff, s[j], m);
    }
    if (sub == 0) {
        float bb = __ldg(b2);
        if (v[3]) {                      // full quad: coalesced float4 store
            *(float4*)(out + eb) = make_float4(s[0] + bb, s[1] + bb,
                                               s[2] + bb, s[3] + bb);
        } else {
#pragma unroll
            for (int j = 0; j < 4; j++)
                if (v[j]) out[eb + j] = s[j] + bb;
        }
    }
}

// ---------------------------------------------------------------------------
// Streams/events created in a static initializer (before harness checkpoints).
struct HxRes {
    cudaStream_t s1, s2;
    cudaEvent_t e0, e1, e2;
    HxRes() {
        cudaStreamCreateWithFlags(&s1, cudaStreamNonBlocking);
        cudaStreamCreateWithFlags(&s2, cudaStreamNonBlocking);
        cudaEventCreateWithFlags(&e0, cudaEventDisableTiming);
        cudaEventCreateWithFlags(&e1, cudaEventDisableTiming);
        cudaEventCreateWithFlags(&e2, cudaEventDisableTiming);
    }
};
static HxRes hx;

// Launch helper: kernel with Programmatic Stream Serialization (PDL secondary).
template <typename F, typename... Args>
static void launch_pdl(F f, dim3 grid, dim3 block, cudaStream_t st, Args... args) {
    cudaLaunchAttribute attr[1];
    attr[0].id = cudaLaunchAttributeProgrammaticStreamSerialization;
    attr[0].val.programmaticStreamSerializationAllowed = 1;
    cudaLaunchConfig_t cfg{};
    cfg.gridDim = grid;
    cfg.blockDim = block;
    cfg.dynamicSmemBytes = 0;
    cfg.stream = st;
    cfg.attrs = attr;
    cfg.numAttrs = 1;
    cudaLaunchKernelEx(&cfg, f, args...);
}

extern "C" void kernel_launch(void* const* d_in, const int* in_sizes, int n_in,
                              void* d_out, int out_size) {
    int off = (n_in >= 13) ? 0 : -1;   // robust to scalar input being dropped
    const void*  ph    = d_in[0];
    const void*  pr    = d_in[1];
    const void*  pt    = d_in[2];
    const float* q     = (const float*)d_in[3];
    const float* ent   = (const float*)d_in[4];
    const float* rel   = (const float*)d_in[6 + off];
    const float* topic = (const float*)d_in[7 + off];
    const float* nont  = (const float*)d_in[8 + off];
    const float* W1    = (const float*)d_in[9 + off];
    const float* b1    = (const float*)d_in[10 + off];
    const float* W2    = (const float*)d_in[11 + off];
    const float* b2    = (const float*)d_in[12 + off];

    int E     = in_sizes[0];
    int Ntext = in_sizes[4] / 128;
    int NREL  = in_sizes[6 + off] / 128;
    int Nn    = in_sizes[7 + off] / 2;
    if (E > E_MAX) E = E_MAX;
    if (Nn > N_MAX) Nn = N_MAX;
    if (NREL > 512) NREL = 512;

    int gE2 = ((E + 1) / 2 + 255) / 256;     // 2 edges per thread
    int nrelb = (NREL + 1) / 2;

    // fork: fill on s1, prep on s2, DDE chain on the main stream
    cudaEventRecord(hx.e0, 0);
    cudaStreamWaitEvent(hx.s1, hx.e0, 0);
    cudaStreamWaitEvent(hx.s2, hx.e0, 0);

    k_fill<<<(Nn * 32 + 255) / 256, 256, 0, hx.s1>>>(ent, nont, Nn, Ntext);
    cudaEventRecord(hx.e1, hx.s1);

    k_prep<<<144 + nrelb, 256, 0, hx.s2>>>(W1, rel, q, b1, NREL);
    cudaEventRecord(hx.e2, hx.s2);

    // PDL chain on the main stream
    k_convert<<<gE2, 256>>>(ph, pr, pt, topic, E);   // ids + DDE round 0 + counts
    launch_pdl(k_scat, dim3(gE2), dim3(256), (cudaStream_t)0, 1, E);  // late trig
    launch_pdl(k_scat, dim3(gE2), dim3(256), (cudaStream_t)0, 2, E);  // EARLY trig

    // gemm: prelaunches on scat2's early trigger; overlaps scat2 with k0..7;
    // tile-8 gated by g_sem. Also needs fill (A) + prep (Wcat) via events.
    cudaStreamWaitEvent(0, hx.e1, 0);
    cudaStreamWaitEvent(0, hx.e2, 0);
    launch_pdl(k_gemm, dim3((Nn + 127) / 128, 2), dim3(256), (cudaStream_t)0,
               topic, Nn, (unsigned)gE2);

    // edge: PDL secondary of gemm; 4 edges per 16-lane group -> E*4 threads
    launch_pdl(k_edge, dim3((E * 4 + 255) / 256), dim3(256), (cudaStream_t)0,
               (float*)d_out, (const float4*)W2, b2, E);
}

// round 15
// speedup vs baseline: 1.0687x; 1.0687x over previous
#include <cuda_runtime.h>
#include <cuda_bf16.h>
#include <cuda_fp16.h>

// ---------------------------------------------------------------------------
// Retriever: out[e] = relu([q | h_e[h] | r_emb[r] | h_e[t]] @ W1 + b1) @ W2 + b2
//   R'     = rel_embs @ W1[270:398] + (q @ W1[0:128] + b1)    (500 x 128, fp16)
//   AB     = h_e @ [W1[128:270] | W1[398:540]]                (N x 256, fp16)
//            single-product fp16 mma.sync GEMM (fp32 accum); DDE columns
//            synthesized into SMEM inside the GEMM (128x128 tile, gridY=2).
//   out[e] = W2 . relu(AB[h,0:128] + AB[t,128:256] + R'[r]) + b2
// NOTES: harness PTX targets plain sm_100 -> tcgen05 unavailable; mma.sync only.
//        R9: DDE kernels are LSU/LTS-throughput bound; batching neutral.
//        R10: 128x256 GEMM tile regressed (mma-issue bound) -> 128x128 kept.
//        R12: griddepsync waits only for the TRIGGER; early triggers race.
//        R13: late triggers everywhere -> serial-equivalent PDL, 149.6us.
//        R7+R14: GEMM/DDE overlap is net-NEGATIVE (L2 contention + occupancy
//        theft), tested via both streams and PDL+semaphore. Serial is final.
//        R15: R13 structure + vectorized id loads (int4/longlong2) in
//        k_edge / k_convert.
// ---------------------------------------------------------------------------

#define E_MAX 500000
#define N_MAX 100000
#define HE_W  144      // row pitch in fp16 for h_e / Wcat (142 used, 2 zero)

__device__ int    g_hh[E_MAX];
__device__ int    g_tt[E_MAX];
__device__ int    g_rr[E_MAX];
__device__ float4 g_f0[N_MAX];                         // fwd r1 sums + cnt_t in .z
__device__ float4 g_r0[N_MAX];                         // rev r1 sums + cnt_h in .z
__device__ float2 g_f1[N_MAX], g_f2[N_MAX];            // fwd rounds 2,3 sums
__device__ float2 g_r1[N_MAX], g_r2[N_MAX];            // rev rounds 2,3 sums
__device__ __half g_hef[(size_t)N_MAX * HE_W];         // h_e fp16 (cols 0..127)
__device__ __half g_wf[256 * HE_W];                    // Wcat fp16, [n][k]
__device__ uint4  g_ab[(size_t)N_MAX * 32];            // AB  [N,256] fp16
__device__ uint4  g_rp[512 * 16];                      // R' [NREL,128] fp16

__device__ __forceinline__ unsigned packh2(float x, float y) {
    __half2 t = __floats2half2_rn(x, y);
    return *(unsigned*)&t;
}
__device__ __forceinline__ float2 h22f(unsigned u) {
    return __half22float2(*(__half2*)&u);
}
__device__ __forceinline__ void red2(float2* p, float x, float y) {
    asm volatile("red.global.add.v2.f32 [%0], {%1, %2};"
                 :: "l"(p), "f"(x), "f"(y) : "memory");
}
__device__ __forceinline__ void red4(float4* p, float x, float y, float z, float w) {
    asm volatile("red.global.add.v4.f32 [%0], {%1, %2, %3, %4};"
                 :: "l"(p), "f"(x), "f"(y), "f"(z), "f"(w) : "memory");
}

// ---------------- build h_e fp16 cols 0..127 + zero DDE state ----------------
__global__ void k_fill(const float* __restrict__ ent, const float* __restrict__ nont,
                       int Nn, int Ntext) {
    int i = blockIdx.x * 256 + threadIdx.x;
    if (i >= Nn * 32) return;
    int node = i >> 5, c4 = i & 31;
    const float* src = (node < Ntext) ? (ent + (size_t)node * 128 + c4 * 4)
                                      : (nont + c4 * 4);
    float4 v = *(const float4*)src;
    *(uint2*)(g_hef + (size_t)node * HE_W + c4 * 4) =
        make_uint2(packh2(v.x, v.y), packh2(v.z, v.w));
    if (c4 == 0) {   // piggyback: zero DDE accumulators
        g_f0[node] = make_float4(0.f, 0.f, 0.f, 0.f);
        g_r0[node] = make_float4(0.f, 0.f, 0.f, 0.f);
        g_f1[node] = make_float2(0.f, 0.f);
        g_f2[node] = make_float2(0.f, 0.f);
        g_r1[node] = make_float2(0.f, 0.f);
        g_r2[node] = make_float2(0.f, 0.f);
    }
}

// ------- ids -> int32 (+dtype detect) + DDE round 0; 2 edges per thread -------
// PDL primary: trigger at the END (after all writes). Vectorized id loads:
// base is even -> longlong2 (int64 ids) / int2 (int32 ids) are aligned.
__global__ void k_convert(const void* ph, const void* pr, const void* pt,
                          const float* __restrict__ topic, int E) {
    __shared__ int s64;
    if (threadIdx.x == 0) {
        // int64 vs int32: int64 view of int32 r-id buffer is >= 2^32 a.s.
        const long long* p = (const long long*)ph;
        const long long* qq = (const long long*)pr;
        int ok = 1;
        for (int i = 0; i < 8; i++) {
            long long v = p[i];  if (v < 0 || v >= 1000000) ok = 0;
            long long w = qq[i]; if (w < 0 || w >= 1000000) ok = 0;
        }
        s64 = ok;
    }
    __syncthreads();
    int base = (blockIdx.x * 256 + threadIdx.x) * 2;
    if (base < E) {
        bool full = (base + 1 < E);
        int h[2], r[2], t[2];
        if (s64) {
            if (full) {
                longlong2 lh = __ldg((const longlong2*)ph + (base >> 1));
                longlong2 lr = __ldg((const longlong2*)pr + (base >> 1));
                longlong2 lt = __ldg((const longlong2*)pt + (base >> 1));
                h[0] = (int)lh.x; h[1] = (int)lh.y;
                r[0] = (int)lr.x; r[1] = (int)lr.y;
                t[0] = (int)lt.x; t[1] = (int)lt.y;
            } else {
                h[0] = h[1] = (int)((const long long*)ph)[base];
                r[0] = r[1] = (int)((const long long*)pr)[base];
                t[0] = t[1] = (int)((const long long*)pt)[base];
            }
        } else {
            if (full) {
                int2 ih = __ldg((const int2*)ph + (base >> 1));
                int2 ir = __ldg((const int2*)pr + (base >> 1));
                int2 it = __ldg((const int2*)pt + (base >> 1));
                h[0] = ih.x; h[1] = ih.y;
                r[0] = ir.x; r[1] = ir.y;
                t[0] = it.x; t[1] = it.y;
            } else {
                h[0] = h[1] = ((const int*)ph)[base];
                r[0] = r[1] = ((const int*)pr)[base];
                t[0] = t[1] = ((const int*)pt)[base];
            }
        }
        const float2* tp2 = (const float2*)topic;
        float2 th0 = __ldg(tp2 + h[0]);
        float2 tt0 = __ldg(tp2 + t[0]);
        float2 th1 = __ldg(tp2 + h[1]);
        float2 tt1 = __ldg(tp2 + t[1]);
        g_hh[base] = h[0]; g_rr[base] = r[0]; g_tt[base] = t[0];
        red4(&g_f0[t[0]], th0.x, th0.y, 1.0f, 0.f);
        red4(&g_r0[h[0]], tt0.x, tt0.y, 1.0f, 0.f);
        if (full) {
            g_hh[base + 1] = h[1]; g_rr[base + 1] = r[1]; g_tt[base + 1] = t[1];
            red4(&g_f0[t[1]], th1.x, th1.y, 1.0f, 0.f);
            red4(&g_r0[h[1]], tt1.x, tt1.y, 1.0f, 0.f);
        }
    }
    cudaTriggerProgrammaticLaunchCompletion();   // AFTER all work (R12 lesson)
}

// ------- DDE scatter round rd (1 or 2); 2 edges per thread --------------------
// PDL secondary + primary: griddepsync at top, trigger at END.
__global__ void k_scat(int rd, int E) {
    cudaGridDependencySynchronize();
    int base = (blockIdx.x * 256 + threadIdx.x) * 2;
    if (base < E) {
        int n2 = (base + 1 < E) ? 2 : 1;
        int e1 = (n2 == 2) ? base + 1 : base;
        int h0 = g_hh[base], t0 = g_tt[base];
        int h1 = g_hh[e1],   t1 = g_tt[e1];
        if (rd == 1) {
            float4 f0h0 = __ldg(&g_f0[h0]);
            float4 r0t0 = __ldg(&g_r0[t0]);
            float4 f0h1 = __ldg(&g_f0[h1]);
            float4 r0t1 = __ldg(&g_r0[t1]);
            float ia = 1.0f / fmaxf(f0h0.z, 1.0f);
            float ib = 1.0f / fmaxf(r0t0.z, 1.0f);
            float ic = 1.0f / fmaxf(f0h1.z, 1.0f);
            float id = 1.0f / fmaxf(r0t1.z, 1.0f);
            red2(&g_f1[t0], f0h0.x * ia, f0h0.y * ia);
            red2(&g_r1[h0], r0t0.x * ib, r0t0.y * ib);
            if (n2 == 2) {
                red2(&g_f1[t1], f0h1.x * ic, f0h1.y * ic);
                red2(&g_r1[h1], r0t1.x * id, r0t1.y * id);
            }
        } else {
            const float* cb = (const float*)g_f0;
            const float* ch = (const float*)g_r0;
            float ca0 = __ldg(cb + 4 * (size_t)h0 + 2);
            float cb0 = __ldg(ch + 4 * (size_t)t0 + 2);
            float ca1 = __ldg(cb + 4 * (size_t)h1 + 2);
            float cb1 = __ldg(ch + 4 * (size_t)t1 + 2);
            float2 f1h0 = __ldg(&g_f1[h0]);
            float2 r1t0 = __ldg(&g_r1[t0]);
            float2 f1h1 = __ldg(&g_f1[h1]);
            float2 r1t1 = __ldg(&g_r1[t1]);
            float ia = 1.0f / fmaxf(ca0, 1.0f);
            float ib = 1.0f / fmaxf(cb0, 1.0f);
            float ic = 1.0f / fmaxf(ca1, 1.0f);
            float id = 1.0f / fmaxf(cb1, 1.0f);
            red2(&g_f2[t0], f1h0.x * ia, f1h0.y * ia);
            red2(&g_r2[h0], r1t0.x * ib, r1t0.y * ib);
            if (n2 == 2) {
                red2(&g_f2[t1], f1h1.x * ic, f1h1.y * ic);
                red2(&g_r2[h1], r1t1.x * id, r1t1.y * id);
            }
        }
    }
    cudaTriggerProgrammaticLaunchCompletion();   // AFTER all work
}

// ------- prep: Wcat fp16 [n][k] | R' = rel@W1_r + (q@W1_q + b1), fp16 ----------
__global__ void k_prep(const float* __restrict__ W1, const float* __restrict__ rel,
                       const float* __restrict__ q, const float* __restrict__ b1,
                       int NREL) {
    int bid = blockIdx.x;
    int tid = threadIdx.x;
    if (bid < 144) {                       // Wcat: 256 elements of the [n][k] array
        int idx = bid * 256 + tid;
        int n = idx / 144, k = idx % 144;
        float v = 0.f;
        if (k < 142) v = (n < 128) ? W1[(128 + k) * 128 + n]
                                   : W1[(398 + k) * 128 + (n - 128)];
        g_wf[idx] = __float2half(v);
    } else {                               // two relations per block
        __shared__ float rs[256];
        __shared__ float qs[128];
        int r = (bid - 144) * 2 + (tid >> 7);
        int j = tid & 127;
        int base = tid & ~127;
        if (tid < 128) qs[tid] = q[tid];
        rs[tid] = (r < NREL) ? rel[(size_t)r * 128 + j] : 0.f;
        __syncthreads();
        if (r < NREL) {
            float accc = b1[j];
#pragma unroll 8
            for (int k = 0; k < 128; k++) accc += qs[k] * __ldg(&W1[k * 128 + j]);
            float accr = 0.f;
#pragma unroll 8
            for (int k = 0; k < 128; k++) accr += rs[base + k] * __ldg(&W1[(270 + k) * 128 + j]);
            ((__half*)g_rp)[(size_t)r * 128 + j] = __float2half(accc + accr);
        }
    }
}

// ---------------------------------------------------------------------------
// GEMM: AB[N,256] = h_e[N,144] @ Wcat[144,256], single-product fp16 mma.sync,
// fp32 accum. Block 128x128 (gridY = n-half), 8 warps (2x4), warp tile 64x32,
// BK=16, cp.async double-buffered; last k-tile synthesized from DDE state.
// PDL: griddepsync before the DDE tile-8 synthesis; trigger at the very END.
// ---------------------------------------------------------------------------
#define APITCH 24   // smem row pitch in fp16 (48B -> conflict-free ldmatrix)
#define R_EL   (128 * APITCH)   // elements per region (3072)

__device__ __forceinline__ void ldsm4(unsigned* r, unsigned a) {
    asm volatile("ldmatrix.sync.aligned.m8n8.x4.shared.b16 {%0,%1,%2,%3}, [%4];"
                 : "=r"(r[0]), "=r"(r[1]), "=r"(r[2]), "=r"(r[3]) : "r"(a));
}
__device__ __forceinline__ void mma_f16(float* d, const unsigned* a, unsigned b0, unsigned b1) {
    asm volatile("mma.sync.aligned.m16n8k16.row.col.f32.f16.f16.f32 "
                 "{%0,%1,%2,%3}, {%4,%5,%6,%7}, {%8,%9}, {%0,%1,%2,%3};"
                 : "+f"(d[0]), "+f"(d[1]), "+f"(d[2]), "+f"(d[3])
                 : "r"(a[0]), "r"(a[1]), "r"(a[2]), "r"(a[3]), "r"(b0), "r"(b1));
}
__device__ __forceinline__ void cp16(unsigned dst, const void* src) {
    asm volatile("cp.async.ca.shared.global [%0], [%1], 16;" :: "r"(dst), "l"(src));
}

__global__ __launch_bounds__(256) void k_gemm(const float* __restrict__ topic, int Nn) {
    // smem regions (fp16 elements): Abuf0 [0,R) Abuf1 [R,2R) Bbuf0 [2R,3R) Bbuf1 [3R,4R)
    __shared__ __align__(16) __half sm[4 * R_EL];     // 24 KB
    unsigned smb = (unsigned)__cvta_generic_to_shared(sm);
    int tid = threadIdx.x;
    int m0 = blockIdx.x * 128, n0 = blockIdx.y * 128;
    int wid = tid >> 5, lane = tid & 31;
    int wm = (wid >> 2) * 64, wn = (wid & 3) * 32;

    // staging: slot 0 = A, slot 1 = B; per tile each thread copies one 16B unit.
    int row = tid >> 1, half = tid & 1;                // 128 rows x 2 halves
    const __half* gbase[2];
    unsigned dstoff[2];                                // bytes, excluding buf
    {
        int gr = m0 + row; if (gr >= Nn) gr = Nn - 1;
        gbase[0] = g_hef + (size_t)gr * HE_W + half * 8;
        gbase[1] = g_wf + (size_t)(n0 + row) * HE_W + half * 8;
        dstoff[0] = (unsigned)(row * APITCH + half * 8) * 2;
        dstoff[1] = (unsigned)(2 * R_EL + row * APITCH + half * 8) * 2;
    }
    const unsigned bufstride = R_EL * 2;               // bytes between buf0/buf1

    float acc[4][4][4];
#pragma unroll
    for (int i = 0; i < 4; i++)
#pragma unroll
        for (int j = 0; j < 4; j++)
#pragma unroll
            for (int k = 0; k < 4; k++) acc[i][j][k] = 0.f;

    int ldrow = lane & 15, ldk = (lane >> 4) * 8;

    // ---- prologue: stage tile 0 into buf 0 ----
    cp16(smb + dstoff[0], gbase[0]);
    cp16(smb + dstoff[1], gbase[1]);
    asm volatile("cp.async.commit_group;");

    for (int it = 0; it <= 8; ++it) {
        int buf = it & 1;
        asm volatile("cp.async.wait_group 0;");
        __syncthreads();

        if (it < 8) {
            unsigned bofs = (buf ^ 1) * bufstride;
            if (it + 1 < 8) {
                cp16(smb + bofs + dstoff[0], gbase[0] + (it + 1) * 16);
                cp16(smb + bofs + dstoff[1], gbase[1] + (it + 1) * 16);
            } else {
                // tile 8 needs scat2's DDE output: full dependency sync first.
                cudaGridDependencySynchronize();
                // B via cp.async (Wcat cols 128..143), A synthesized
                cp16(smb + bofs + dstoff[1], gbase[1] + 8 * 16);
                int i = m0 + row; if (i >= Nn) i = Nn - 1;
                float v[8];
                if (half == 0) {  // cols 128..135: topic, fwd rounds 1..3
                    float2 tp = __ldg(((const float2*)topic) + i);
                    float4 f0 = g_f0[i];
                    float2 f1 = g_f1[i], f2 = g_f2[i];
                    float ict = 1.0f / fmaxf(f0.z, 1.0f);
                    v[0] = tp.x;       v[1] = tp.y;
                    v[2] = f0.x * ict; v[3] = f0.y * ict;
                    v[4] = f1.x * ict; v[5] = f1.y * ict;
                    v[6] = f2.x * ict; v[7] = f2.y * ict;
                } else {          // cols 136..143: rev rounds 1..3, pad
                    float4 r0 = g_r0[i];
                    float2 r1 = g_r1[i], r2 = g_r2[i];
                    float ich = 1.0f / fmaxf(r0.z, 1.0f);
                    v[0] = r0.x * ich; v[1] = r0.y * ich;
                    v[2] = r1.x * ich; v[3] = r1.y * ich;
                    v[4] = r2.x * ich; v[5] = r2.y * ich;
                    v[6] = 0.f;        v[7] = 0.f;
                }
                *(uint4*)((char*)sm + bofs + dstoff[0]) =
                    make_uint4(packh2(v[0], v[1]), packh2(v[2], v[3]),
                               packh2(v[4], v[5]), packh2(v[6], v[7]));
            }
            asm volatile("cp.async.commit_group;");
        }

        // ---- fragments from buf ----
        unsigned aoff = buf * bufstride;
        unsigned Af[4][4], Bf[2][4];
#pragma unroll
        for (int mf = 0; mf < 4; mf++) {
            unsigned r = (wm + mf * 16 + ldrow) * APITCH + ldk;
            ldsm4(Af[mf], smb + aoff + r * 2);
        }
#pragma unroll
        for (int nh = 0; nh < 2; nh++) {
            unsigned r = (wn + nh * 16 + ldrow) * APITCH + ldk;
            ldsm4(Bf[nh], smb + 2 * R_EL * 2 + aoff + r * 2);
        }
#pragma unroll
        for (int mf = 0; mf < 4; mf++)
#pragma unroll
            for (int nf = 0; nf < 4; nf++) {
                int nh = nf >> 1, sel = nf & 1;
                mma_f16(acc[mf][nf], Af[mf], Bf[nh][sel], Bf[nh][sel + 2]);
            }
        if (it < 8) __syncthreads();
    }

    // ---- epilogue: fp32 acc -> fp16 AB ----
    int g = lane >> 2, tg = lane & 3;
    unsigned* outw = (unsigned*)g_ab;
#pragma unroll
    for (int mf = 0; mf < 4; mf++)
#pragma unroll
        for (int nf = 0; nf < 4; nf++) {
            int col = n0 + wn + nf * 8 + 2 * tg;
            int r0 = m0 + wm + mf * 16 + g;
            if (r0 < Nn)
                outw[(size_t)r0 * 128 + (col >> 1)] = packh2(acc[mf][nf][0], acc[mf][nf][1]);
            int r1 = r0 + 8;
            if (r1 < Nn)
                outw[(size_t)r1 * 128 + (col >> 1)] = packh2(acc[mf][nf][2], acc[mf][nf][3]);
        }
    cudaTriggerProgrammaticLaunchCompletion();   // AFTER epilogue stores
}

// -------- edge stage: 4 edges per 16-lane group, 12 batched uint4 gathers -----
// PDL secondary of gemm: ids (int4-vectorized) / R' / W2 loaded BEFORE
// griddepsync, overlapping gemm's drain; AB gathers after.
__device__ __forceinline__ float edge_dot(uint4 ua, uint4 ub, uint4 ur,
                                          float4 w0, float4 w1) {
    float2 a0 = h22f(ua.x), a1 = h22f(ua.y), a2 = h22f(ua.z), a3 = h22f(ua.w);
    float2 b0 = h22f(ub.x), b1 = h22f(ub.y), b2 = h22f(ub.z), b3 = h22f(ub.w);
    float2 c0 = h22f(ur.x), c1 = h22f(ur.y), c2 = h22f(ur.z), c3 = h22f(ur.w);
    return fmaxf(a0.x + b0.x + c0.x, 0.f) * w0.x
         + fmaxf(a0.y + b0.y + c0.y, 0.f) * w0.y
         + fmaxf(a1.x + b1.x + c1.x, 0.f) * w0.z
         + fmaxf(a1.y + b1.y + c1.y, 0.f) * w0.w
         + fmaxf(a2.x + b2.x + c2.x, 0.f) * w1.x
         + fmaxf(a2.y + b2.y + c2.y, 0.f) * w1.y
         + fmaxf(a3.x + b3.x + c3.x, 0.f) * w1.z
         + fmaxf(a3.y + b3.y + c3.y, 0.f) * w1.w;
}

__global__ __launch_bounds__(256) void k_edge(float* __restrict__ out,
                                              const float4* __restrict__ w2,
                                              const float* __restrict__ b2, int E) {
    int gt = blockIdx.x * 256 + threadIdx.x;
    int quad = gt >> 4, sub = gt & 15;
    int eb = quad * 4;
    if (eb >= E) { cudaGridDependencySynchronize(); return; }
    bool tail = (eb + 3 >= E);
    int hh[4], tt[4], rr[4];
    if (!tail) {     // eb multiple of 4 -> int4 loads are aligned
        int4 ih = __ldg((const int4*)(g_hh + eb));
        int4 it = __ldg((const int4*)(g_tt + eb));
        int4 ir = __ldg((const int4*)(g_rr + eb));
        hh[0] = ih.x; hh[1] = ih.y; hh[2] = ih.z; hh[3] = ih.w;
        tt[0] = it.x; tt[1] = it.y; tt[2] = it.z; tt[3] = it.w;
        rr[0] = ir.x; rr[1] = ir.y; rr[2] = ir.z; rr[3] = ir.w;
    } else {
#pragma unroll
        for (int j = 0; j < 4; j++) {
            int e = (eb + j < E) ? eb + j : E - 1;
            hh[j] = g_hh[e]; tt[j] = g_tt[e]; rr[j] = g_rr[e];
        }
    }
    // pre-sync: R' gathers + W2 (complete before gemm launched)
    uint4 ur[4];
#pragma unroll
    for (int j = 0; j < 4; j++) ur[j] = __ldg(&g_rp[(size_t)rr[j] * 16 + sub]);
    float4 w0 = __ldg(&w2[2 * sub]);
    float4 w1 = __ldg(&w2[2 * sub + 1]);

    cudaGridDependencySynchronize();   // AB (gemm output) ready after this

    uint4 ua[4], ub[4];
#pragma unroll
    for (int j = 0; j < 4; j++) ua[j] = __ldg(&g_ab[(size_t)hh[j] * 32 + sub]);
#pragma unroll
    for (int j = 0; j < 4; j++) ub[j] = __ldg(&g_ab[(size_t)tt[j] * 32 + 16 + sub]);

    float s[4];
#pragma unroll
    for (int j = 0; j < 4; j++) s[j] = edge_dot(ua[j], ub[j], ur[j], w0, w1);
#pragma unroll
    for (int m = 8; m >= 1; m >>= 1) {
#pragma unroll
        for (int j = 0; j < 4; j++) s[j] += __shfl_xor_sync(0xffffffff, s[j], m);
    }
    if (sub == 0) {
        float bb = __ldg(b2);
        if (!tail) {                     // full quad: coalesced float4 store
            *(float4*)(out + eb) = make_float4(s[0] + bb, s[1] + bb,
                                               s[2] + bb, s[3] + bb);
        } else {
#pragma unroll
            for (int j = 0; j < 4; j++)
                if (eb + j < E) out[eb + j] = s[j] + bb;
        }
    }
}

// ---------------------------------------------------------------------------
// Streams/events created in a static initializer (before harness checkpoints).
struct HxRes {
    cudaStream_t s1, s2;
    cudaEvent_t e0, e1, e2;
    HxRes() {
        cudaStreamCreateWithFlags(&s1, cudaStreamNonBlocking);
        cudaStreamCreateWithFlags(&s2, cudaStreamNonBlocking);
        cudaEventCreateWithFlags(&e0, cudaEventDisableTiming);
        cudaEventCreateWithFlags(&e1, cudaEventDisableTiming);
        cudaEventCreateWithFlags(&e2, cudaEventDisableTiming);
    }
};
static HxRes hx;

// Launch helper: kernel with Programmatic Stream Serialization (PDL secondary).
template <typename F, typename... Args>
static void launch_pdl(F f, dim3 grid, dim3 block, cudaStream_t st, Args... args) {
    cudaLaunchAttribute attr[1];
    attr[0].id = cudaLaunchAttributeProgrammaticStreamSerialization;
    attr[0].val.programmaticStreamSerializationAllowed = 1;
    cudaLaunchConfig_t cfg{};
    cfg.gridDim = grid;
    cfg.blockDim = block;
    cfg.dynamicSmemBytes = 0;
    cfg.stream = st;
    cfg.attrs = attr;
    cfg.numAttrs = 1;
    cudaLaunchKernelEx(&cfg, f, args...);
}

extern "C" void kernel_launch(void* const* d_in, const int* in_sizes, int n_in,
                              void* d_out, int out_size) {
    int off = (n_in >= 13) ? 0 : -1;   // robust to scalar input being dropped
    const void*  ph    = d_in[0];
    const void*  pr    = d_in[1];
    const void*  pt    = d_in[2];
    const float* q     = (const float*)d_in[3];
    const float* ent   = (const float*)d_in[4];
    const float* rel   = (const float*)d_in[6 + off];
    const float* topic = (const float*)d_in[7 + off];
    const float* nont  = (const float*)d_in[8 + off];
    const float* W1    = (const float*)d_in[9 + off];
    const float* b1    = (const float*)d_in[10 + off];
    const float* W2    = (const float*)d_in[11 + off];
    const float* b2    = (const float*)d_in[12 + off];

    int E     = in_sizes[0];
    int Ntext = in_sizes[4] / 128;
    int NREL  = in_sizes[6 + off] / 128;
    int Nn    = in_sizes[7 + off] / 2;
    if (E > E_MAX) E = E_MAX;
    if (Nn > N_MAX) Nn = N_MAX;
    if (NREL > 512) NREL = 512;

    int gE2 = ((E + 1) / 2 + 255) / 256;     // 2 edges per thread
    int nrelb = (NREL + 1) / 2;

    // fork: fill on s1, prep on s2, DDE chain on the main stream
    cudaEventRecord(hx.e0, 0);
    cudaStreamWaitEvent(hx.s1, hx.e0, 0);
    cudaStreamWaitEvent(hx.s2, hx.e0, 0);

    k_fill<<<(Nn * 32 + 255) / 256, 256, 0, hx.s1>>>(ent, nont, Nn, Ntext);
    cudaEventRecord(hx.e1, hx.s1);

    k_prep<<<144 + nrelb, 256, 0, hx.s2>>>(W1, rel, q, b1, NREL);
    cudaEventRecord(hx.e2, hx.s2);

    // PDL chain on the main stream (late triggers -> serial-equivalent data flow)
    k_convert<<<gE2, 256>>>(ph, pr, pt, topic, E);   // ids + DDE round 0 + counts
    launch_pdl(k_scat, dim3(gE2), dim3(256), (cudaStream_t)0, 1, E);
    launch_pdl(k_scat, dim3(gE2), dim3(256), (cudaStream_t)0, 2, E);

    // gemm needs fill (A), prep (Wcat) and the DDE chain
    cudaStreamWaitEvent(0, hx.e1, 0);
    cudaStreamWaitEvent(0, hx.e2, 0);
    launch_pdl(k_gemm, dim3((Nn + 127) / 128, 2), dim3(256), (cudaStream_t)0,
               topic, Nn);

    // edge: PDL secondary of gemm; 4 edges per 16-lane group -> E*4 threads
    launch_pdl(k_edge, dim3((E * 4 + 255) / 256), dim3(256), (cudaStream_t)0,
               (float*)d_out, (const float4*)W2, b2, E);
}

// round 16
// speedup vs baseline: 1.0991x; 1.0284x over previous
#include <cuda_runtime.h>
#include <cuda_bf16.h>
#include <cuda_fp16.h>

// ---------------------------------------------------------------------------
// Retriever: out[e] = relu([q | h_e[h] | r_emb[r] | h_e[t]] @ W1 + b1) @ W2 + b2
//   R'     = rel_embs @ W1[270:398] + (q @ W1[0:128] + b1)    (500 x 128, fp16)
//   AB     = h_e @ [W1[128:270] | W1[398:540]]                (N x 256, fp16)
//            single-product fp16 mma.sync GEMM (fp32 accum); DDE columns
//            synthesized into SMEM inside the GEMM (128x128 tile, gridY=2).
//   out[e] = W2 . relu(AB[h,0:128] + AB[t,128:256] + R'[r]) + b2
// NOTES: harness PTX targets plain sm_100 -> tcgen05 unavailable; mma.sync only.
//        R9: DDE kernels are LSU/LTS-throughput bound.
//        R10: 128x256 GEMM tile regressed (mma-issue bound) -> 128x128 kept.
//        R12: griddepsync waits only for the TRIGGER; early triggers race.
//        R13: late triggers everywhere -> serial-equivalent PDL chain.
//        R7+R14: GEMM/DDE overlap net-NEGATIVE (L2 contention + occupancy
//        theft) via both streams and PDL+semaphore. Serial is final.
//        R16: ids packed into ONE uint64 (h|t<<17|r<<34) -> halves the
//        scattered id-load count in the LSU-bound scat kernels, 1 store in
//        convert, 2 vector id loads in edge.
// ---------------------------------------------------------------------------

#define E_MAX 500000
#define N_MAX 100000
#define HE_W  144      // row pitch in fp16 for h_e / Wcat (142 used, 2 zero)

__device__ unsigned long long g_pk[E_MAX];             // packed h|t<<17|r<<34
__device__ float4 g_f0[N_MAX];                         // fwd r1 sums + cnt_t in .z
__device__ float4 g_r0[N_MAX];                         // rev r1 sums + cnt_h in .z
__device__ float2 g_f1[N_MAX], g_f2[N_MAX];            // fwd rounds 2,3 sums
__device__ float2 g_r1[N_MAX], g_r2[N_MAX];            // rev rounds 2,3 sums
__device__ __half g_hef[(size_t)N_MAX * HE_W];         // h_e fp16 (cols 0..127)
__device__ __half g_wf[256 * HE_W];                    // Wcat fp16, [n][k]
__device__ uint4  g_ab[(size_t)N_MAX * 32];            // AB  [N,256] fp16
__device__ uint4  g_rp[512 * 16];                      // R' [NREL,128] fp16

__device__ __forceinline__ unsigned long long packid(int h, int t, int r) {
    return (unsigned long long)(unsigned)h
         | ((unsigned long long)(unsigned)t << 17)
         | ((unsigned long long)(unsigned)r << 34);
}
#define UNPK_H(p) ((int)((p) & 0x1FFFFULL))
#define UNPK_T(p) ((int)(((p) >> 17) & 0x1FFFFULL))
#define UNPK_R(p) ((int)(((p) >> 34) & 0x3FFULL))

__device__ __forceinline__ unsigned packh2(float x, float y) {
    __half2 t = __floats2half2_rn(x, y);
    return *(unsigned*)&t;
}
__device__ __forceinline__ float2 h22f(unsigned u) {
    return __half22float2(*(__half2*)&u);
}
__device__ __forceinline__ void red2(float2* p, float x, float y) {
    asm volatile("red.global.add.v2.f32 [%0], {%1, %2};"
                 :: "l"(p), "f"(x), "f"(y) : "memory");
}
__device__ __forceinline__ void red4(float4* p, float x, float y, float z, float w) {
    asm volatile("red.global.add.v4.f32 [%0], {%1, %2, %3, %4};"
                 :: "l"(p), "f"(x), "f"(y), "f"(z), "f"(w) : "memory");
}

// ---------------- build h_e fp16 cols 0..127 + zero DDE state ----------------
__global__ void k_fill(const float* __restrict__ ent, const float* __restrict__ nont,
                       int Nn, int Ntext) {
    int i = blockIdx.x * 256 + threadIdx.x;
    if (i >= Nn * 32) return;
    int node = i >> 5, c4 = i & 31;
    const float* src = (node < Ntext) ? (ent + (size_t)node * 128 + c4 * 4)
                                      : (nont + c4 * 4);
    float4 v = *(const float4*)src;
    *(uint2*)(g_hef + (size_t)node * HE_W + c4 * 4) =
        make_uint2(packh2(v.x, v.y), packh2(v.z, v.w));
    if (c4 == 0) {   // piggyback: zero DDE accumulators
        g_f0[node] = make_float4(0.f, 0.f, 0.f, 0.f);
        g_r0[node] = make_float4(0.f, 0.f, 0.f, 0.f);
        g_f1[node] = make_float2(0.f, 0.f);
        g_f2[node] = make_float2(0.f, 0.f);
        g_r1[node] = make_float2(0.f, 0.f);
        g_r2[node] = make_float2(0.f, 0.f);
    }
}

// ------- ids -> packed uint64 (+dtype detect) + DDE round 0; 2 edges/thread ---
// PDL primary: trigger at the END (after all writes).
__global__ void k_convert(const void* ph, const void* pr, const void* pt,
                          const float* __restrict__ topic, int E) {
    __shared__ int s64;
    if (threadIdx.x == 0) {
        // int64 vs int32: int64 view of int32 r-id buffer is >= 2^32 a.s.
        const long long* p = (const long long*)ph;
        const long long* qq = (const long long*)pr;
        int ok = 1;
        for (int i = 0; i < 8; i++) {
            long long v = p[i];  if (v < 0 || v >= 1000000) ok = 0;
            long long w = qq[i]; if (w < 0 || w >= 1000000) ok = 0;
        }
        s64 = ok;
    }
    __syncthreads();
    int base = (blockIdx.x * 256 + threadIdx.x) * 2;
    if (base < E) {
        bool full = (base + 1 < E);
        int h[2], r[2], t[2];
        if (s64) {
            if (full) {
                longlong2 lh = __ldg((const longlong2*)ph + (base >> 1));
                longlong2 lr = __ldg((const longlong2*)pr + (base >> 1));
                longlong2 lt = __ldg((const longlong2*)pt + (base >> 1));
                h[0] = (int)lh.x; h[1] = (int)lh.y;
                r[0] = (int)lr.x; r[1] = (int)lr.y;
                t[0] = (int)lt.x; t[1] = (int)lt.y;
            } else {
                h[0] = h[1] = (int)((const long long*)ph)[base];
                r[0] = r[1] = (int)((const long long*)pr)[base];
                t[0] = t[1] = (int)((const long long*)pt)[base];
            }
        } else {
            if (full) {
                int2 ih = __ldg((const int2*)ph + (base >> 1));
                int2 ir = __ldg((const int2*)pr + (base >> 1));
                int2 it = __ldg((const int2*)pt + (base >> 1));
                h[0] = ih.x; h[1] = ih.y;
                r[0] = ir.x; r[1] = ir.y;
                t[0] = it.x; t[1] = it.y;
            } else {
                h[0] = h[1] = ((const int*)ph)[base];
                r[0] = r[1] = ((const int*)pr)[base];
                t[0] = t[1] = ((const int*)pt)[base];
            }
        }
        const float2* tp2 = (const float2*)topic;
        float2 th0 = __ldg(tp2 + h[0]);
        float2 tt0 = __ldg(tp2 + t[0]);
        float2 th1 = __ldg(tp2 + h[1]);
        float2 tt1 = __ldg(tp2 + t[1]);
        if (full) {
            *(longlong2*)(g_pk + base) = make_longlong2(
                (long long)packid(h[0], t[0], r[0]),
                (long long)packid(h[1], t[1], r[1]));
        } else {
            g_pk[base] = packid(h[0], t[0], r[0]);
        }
        red4(&g_f0[t[0]], th0.x, th0.y, 1.0f, 0.f);
        red4(&g_r0[h[0]], tt0.x, tt0.y, 1.0f, 0.f);
        if (full) {
            red4(&g_f0[t[1]], th1.x, th1.y, 1.0f, 0.f);
            red4(&g_r0[h[1]], tt1.x, tt1.y, 1.0f, 0.f);
        }
    }
    cudaTriggerProgrammaticLaunchCompletion();   // AFTER all work (R12 lesson)
}

// ------- DDE scatter round rd (1 or 2); 2 edges per thread --------------------
// PDL secondary + primary: griddepsync at top, trigger at END.
// ONE longlong2 load yields h,t for both edges (was 4 scattered int loads).
__global__ void k_scat(int rd, int E) {
    cudaGridDependencySynchronize();
    int base = (blockIdx.x * 256 + threadIdx.x) * 2;
    if (base < E) {
        bool full = (base + 1 < E);
        unsigned long long p0, p1;
        if (full) {
            longlong2 lp = __ldg((const longlong2*)(g_pk + base));
            p0 = (unsigned long long)lp.x;
            p1 = (unsigned long long)lp.y;
        } else {
            p0 = p1 = g_pk[base];
        }
        int h0 = UNPK_H(p0), t0 = UNPK_T(p0);
        int h1 = UNPK_H(p1), t1 = UNPK_T(p1);
        if (rd == 1) {
            float4 f0h0 = __ldg(&g_f0[h0]);
            float4 r0t0 = __ldg(&g_r0[t0]);
            float4 f0h1 = __ldg(&g_f0[h1]);
            float4 r0t1 = __ldg(&g_r0[t1]);
            float ia = 1.0f / fmaxf(f0h0.z, 1.0f);
            float ib = 1.0f / fmaxf(r0t0.z, 1.0f);
            float ic = 1.0f / fmaxf(f0h1.z, 1.0f);
            float id = 1.0f / fmaxf(r0t1.z, 1.0f);
            red2(&g_f1[t0], f0h0.x * ia, f0h0.y * ia);
            red2(&g_r1[h0], r0t0.x * ib, r0t0.y * ib);
            if (full) {
                red2(&g_f1[t1], f0h1.x * ic, f0h1.y * ic);
                red2(&g_r1[h1], r0t1.x * id, r0t1.y * id);
            }
        } else {
            const float* cb = (const float*)g_f0;
            const float* ch = (const float*)g_r0;
            float ca0 = __ldg(cb + 4 * (size_t)h0 + 2);
            float cb0 = __ldg(ch + 4 * (size_t)t0 + 2);
            float ca1 = __ldg(cb + 4 * (size_t)h1 + 2);
            float cb1 = __ldg(ch + 4 * (size_t)t1 + 2);
            float2 f1h0 = __ldg(&g_f1[h0]);
            float2 r1t0 = __ldg(&g_r1[t0]);
            float2 f1h1 = __ldg(&g_f1[h1]);
            float2 r1t1 = __ldg(&g_r1[t1]);
            float ia = 1.0f / fmaxf(ca0, 1.0f);
            float ib = 1.0f / fmaxf(cb0, 1.0f);
            float ic = 1.0f / fmaxf(ca1, 1.0f);
            float id = 1.0f / fmaxf(cb1, 1.0f);
            red2(&g_f2[t0], f1h0.x * ia, f1h0.y * ia);
            red2(&g_r2[h0], r1t0.x * ib, r1t0.y * ib);
            if (full) {
                red2(&g_f2[t1], f1h1.x * ic, f1h1.y * ic);
                red2(&g_r2[h1], r1t1.x * id, r1t1.y * id);
            }
        }
    }
    cudaTriggerProgrammaticLaunchCompletion();   // AFTER all work
}

// ------- prep: Wcat fp16 [n][k] | R' = rel@W1_r + (q@W1_q + b1), fp16 ----------
__global__ void k_prep(const float* __restrict__ W1, const float* __restrict__ rel,
                       const float* __restrict__ q, const float* __restrict__ b1,
                       int NREL) {
    int bid = blockIdx.x;
    int tid = threadIdx.x;
    if (bid < 144) {                       // Wcat: 256 elements of the [n][k] array
        int idx = bid * 256 + tid;
        int n = idx / 144, k = idx % 144;
        float v = 0.f;
        if (k < 142) v = (n < 128) ? W1[(128 + k) * 128 + n]
                                   : W1[(398 + k) * 128 + (n - 128)];
        g_wf[idx] = __float2half(v);
    } else {                               // two relations per block
        __shared__ float rs[256];
        __shared__ float qs[128];
        int r = (bid - 144) * 2 + (tid >> 7);
        int j = tid & 127;
        int base = tid & ~127;
        if (tid < 128) qs[tid] = q[tid];
        rs[tid] = (r < NREL) ? rel[(size_t)r * 128 + j] : 0.f;
        __syncthreads();
        if (r < NREL) {
            float accc = b1[j];
#pragma unroll 8
            for (int k = 0; k < 128; k++) accc += qs[k] * __ldg(&W1[k * 128 + j]);
            float accr = 0.f;
#pragma unroll 8
            for (int k = 0; k < 128; k++) accr += rs[base + k] * __ldg(&W1[(270 + k) * 128 + j]);
            ((__half*)g_rp)[(size_t)r * 128 + j] = __float2half(accc + accr);
        }
    }
}

// ---------------------------------------------------------------------------
// GEMM: AB[N,256] = h_e[N,144] @ Wcat[144,256], single-product fp16 mma.sync,
// fp32 accum. Block 128x128 (gridY = n-half), 8 warps (2x4), warp tile 64x32,
// BK=16, cp.async double-buffered; last k-tile synthesized from DDE state.
// PDL: griddepsync before the DDE tile-8 synthesis; trigger at the very END.
// ---------------------------------------------------------------------------
#define APITCH 24   // smem row pitch in fp16 (48B -> conflict-free ldmatrix)
#define R_EL   (128 * APITCH)   // elements per region (3072)

__device__ __forceinline__ void ldsm4(unsigned* r, unsigned a) {
    asm volatile("ldmatrix.sync.aligned.m8n8.x4.shared.b16 {%0,%1,%2,%3}, [%4];"
                 : "=r"(r[0]), "=r"(r[1]), "=r"(r[2]), "=r"(r[3]) : "r"(a));
}
__device__ __forceinline__ void mma_f16(float* d, const unsigned* a, unsigned b0, unsigned b1) {
    asm volatile("mma.sync.aligned.m16n8k16.row.col.f32.f16.f16.f32 "
                 "{%0,%1,%2,%3}, {%4,%5,%6,%7}, {%8,%9}, {%0,%1,%2,%3};"
                 : "+f"(d[0]), "+f"(d[1]), "+f"(d[2]), "+f"(d[3])
                 : "r"(a[0]), "r"(a[1]), "r"(a[2]), "r"(a[3]), "r"(b0), "r"(b1));
}
__device__ __forceinline__ void cp16(unsigned dst, const void* src) {
    asm volatile("cp.async.ca.shared.global [%0], [%1], 16;" :: "r"(dst), "l"(src));
}

__global__ __launch_bounds__(256) void k_gemm(const float* __restrict__ topic, int Nn) {
    // smem regions (fp16 elements): Abuf0 [0,R) Abuf1 [R,2R) Bbuf0 [2R,3R) Bbuf1 [3R,4R)
    __shared__ __align__(16) __half sm[4 * R_EL];     // 24 KB
    unsigned smb = (unsigned)__cvta_generic_to_shared(sm);
    int tid = threadIdx.x;
    int m0 = blockIdx.x * 128, n0 = blockIdx.y * 128;
    int wid = tid >> 5, lane = tid & 31;
    int wm = (wid >> 2) * 64, wn = (wid & 3) * 32;

    // staging: slot 0 = A, slot 1 = B; per tile each thread copies one 16B unit.
    int row = tid >> 1, half = tid & 1;                // 128 rows x 2 halves
    const __half* gbase[2];
    unsigned dstoff[2];                                // bytes, excluding buf
    {
        int gr = m0 + row; if (gr >= Nn) gr = Nn - 1;
        gbase[0] = g_hef + (size_t)gr * HE_W + half * 8;
        gbase[1] = g_wf + (size_t)(n0 + row) * HE_W + half * 8;
        dstoff[0] = (unsigned)(row * APITCH + half * 8) * 2;
        dstoff[1] = (unsigned)(2 * R_EL + row * APITCH + half * 8) * 2;
    }
    const unsigned bufstride = R_EL * 2;               // bytes between buf0/buf1

    float acc[4][4][4];
#pragma unroll
    for (int i = 0; i < 4; i++)
#pragma unroll
        for (int j = 0; j < 4; j++)
#pragma unroll
            for (int k = 0; k < 4; k++) acc[i][j][k] = 0.f;

    int ldrow = lane & 15, ldk = (lane >> 4) * 8;

    // ---- prologue: stage tile 0 into buf 0 ----
    cp16(smb + dstoff[0], gbase[0]);
    cp16(smb + dstoff[1], gbase[1]);
    asm volatile("cp.async.commit_group;");

    for (int it = 0; it <= 8; ++it) {
        int buf = it & 1;
        asm volatile("cp.async.wait_group 0;");
        __syncthreads();

        if (it < 8) {
            unsigned bofs = (buf ^ 1) * bufstride;
            if (it + 1 < 8) {
                cp16(smb + bofs + dstoff[0], gbase[0] + (it + 1) * 16);
                cp16(smb + bofs + dstoff[1], gbase[1] + (it + 1) * 16);
            } else {
                // tile 8 needs scat2's DDE output: full dependency sync first.
                cudaGridDependencySynchronize();
                // B via cp.async (Wcat cols 128..143), A synthesized
                cp16(smb + bofs + dstoff[1], gbase[1] + 8 * 16);
                int i = m0 + row; if (i >= Nn) i = Nn - 1;
                float v[8];
                if (half == 0) {  // cols 128..135: topic, fwd rounds 1..3
                    float2 tp = __ldg(((const float2*)topic) + i);
                    float4 f0 = g_f0[i];
                    float2 f1 = g_f1[i], f2 = g_f2[i];
                    float ict = 1.0f / fmaxf(f0.z, 1.0f);
                    v[0] = tp.x;       v[1] = tp.y;
                    v[2] = f0.x * ict; v[3] = f0.y * ict;
                    v[4] = f1.x * ict; v[5] = f1.y * ict;
                    v[6] = f2.x * ict; v[7] = f2.y * ict;
                } else {          // cols 136..143: rev rounds 1..3, pad
                    float4 r0 = g_r0[i];
                    float2 r1 = g_r1[i], r2 = g_r2[i];
                    float ich = 1.0f / fmaxf(r0.z, 1.0f);
                    v[0] = r0.x * ich; v[1] = r0.y * ich;
                    v[2] = r1.x * ich; v[3] = r1.y * ich;
                    v[4] = r2.x * ich; v[5] = r2.y * ich;
                    v[6] = 0.f;        v[7] = 0.f;
                }
                *(uint4*)((char*)sm + bofs + dstoff[0]) =
                    make_uint4(packh2(v[0], v[1]), packh2(v[2], v[3]),
                               packh2(v[4], v[5]), packh2(v[6], v[7]));
            }
            asm volatile("cp.async.commit_group;");
        }

        // ---- fragments from buf ----
        unsigned aoff = buf * bufstride;
        unsigned Af[4][4], Bf[2][4];
#pragma unroll
        for (int mf = 0; mf < 4; mf++) {
            unsigned r = (wm + mf * 16 + ldrow) * APITCH + ldk;
            ldsm4(Af[mf], smb + aoff + r * 2);
        }
#pragma unroll
        for (int nh = 0; nh < 2; nh++) {
            unsigned r = (wn + nh * 16 + ldrow) * APITCH + ldk;
            ldsm4(Bf[nh], smb + 2 * R_EL * 2 + aoff + r * 2);
        }
#pragma unroll
        for (int mf = 0; mf < 4; mf++)
#pragma unroll
            for (int nf = 0; nf < 4; nf++) {
                int nh = nf >> 1, sel = nf & 1;
                mma_f16(acc[mf][nf], Af[mf], Bf[nh][sel], Bf[nh][sel + 2]);
            }
        if (it < 8) __syncthreads();
    }

    // ---- epilogue: fp32 acc -> fp16 AB ----
    int g = lane >> 2, tg = lane & 3;
    unsigned* outw = (unsigned*)g_ab;
#pragma unroll
    for (int mf = 0; mf < 4; mf++)
#pragma unroll
        for (int nf = 0; nf < 4; nf++) {
            int col = n0 + wn + nf * 8 + 2 * tg;
            int r0 = m0 + wm + mf * 16 + g;
            if (r0 < Nn)
                outw[(size_t)r0 * 128 + (col >> 1)] = packh2(acc[mf][nf][0], acc[mf][nf][1]);
            int r1 = r0 + 8;
            if (r1 < Nn)
                outw[(size_t)r1 * 128 + (col >> 1)] = packh2(acc[mf][nf][2], acc[mf][nf][3]);
        }
    cudaTriggerProgrammaticLaunchCompletion();   // AFTER epilogue stores
}

// -------- edge stage: 4 edges per 16-lane group, 12 batched uint4 gathers -----
// PDL secondary of gemm: packed ids / R' / W2 loaded BEFORE griddepsync,
// overlapping gemm's drain; AB gathers after.
__device__ __forceinline__ float edge_dot(uint4 ua, uint4 ub, uint4 ur,
                                          float4 w0, float4 w1) {
    float2 a0 = h22f(ua.x), a1 = h22f(ua.y), a2 = h22f(ua.z), a3 = h22f(ua.w);
    float2 b0 = h22f(ub.x), b1 = h22f(ub.y), b2 = h22f(ub.z), b3 = h22f(ub.w);
    float2 c0 = h22f(ur.x), c1 = h22f(ur.y), c2 = h22f(ur.z), c3 = h22f(ur.w);
    return fmaxf(a0.x + b0.x + c0.x, 0.f) * w0.x
         + fmaxf(a0.y + b0.y + c0.y, 0.f) * w0.y
         + fmaxf(a1.x + b1.x + c1.x, 0.f) * w0.z
         + fmaxf(a1.y + b1.y + c1.y, 0.f) * w0.w
         + fmaxf(a2.x + b2.x + c2.x, 0.f) * w1.x
         + fmaxf(a2.y + b2.y + c2.y, 0.f) * w1.y
         + fmaxf(a3.x + b3.x + c3.x, 0.f) * w1.z
         + fmaxf(a3.y + b3.y + c3.y, 0.f) * w1.w;
}

__global__ __launch_bounds__(256) void k_edge(float* __restrict__ out,
                                              const float4* __restrict__ w2,
                                              const float* __restrict__ b2, int E) {
    int gt = blockIdx.x * 256 + threadIdx.x;
    int quad = gt >> 4, sub = gt & 15;
    int eb = quad * 4;
    if (eb >= E) { cudaGridDependencySynchronize(); return; }
    bool tail = (eb + 3 >= E);
    unsigned long long pk[4];
    if (!tail) {     // eb multiple of 4 -> 32B-aligned longlong2 pair
        longlong2 l0 = __ldg((const longlong2*)(g_pk + eb));
        longlong2 l1 = __ldg((const longlong2*)(g_pk + eb + 2));
        pk[0] = (unsigned long long)l0.x; pk[1] = (unsigned long long)l0.y;
        pk[2] = (unsigned long long)l1.x; pk[3] = (unsigned long long)l1.y;
    } else {
#pragma unroll
        for (int j = 0; j < 4; j++) {
            int e = (eb + j < E) ? eb + j : E - 1;
            pk[j] = g_pk[e];
        }
    }
    int hh[4], tt[4], rr[4];
#pragma unroll
    for (int j = 0; j < 4; j++) {
        hh[j] = UNPK_H(pk[j]); tt[j] = UNPK_T(pk[j]); rr[j] = UNPK_R(pk[j]);
    }
    // pre-sync: R' gathers + W2 (complete before gemm launched)
    uint4 ur[4];
#pragma unroll
    for (int j = 0; j < 4; j++) ur[j] = __ldg(&g_rp[(size_t)rr[j] * 16 + sub]);
    float4 w0 = __ldg(&w2[2 * sub]);
    float4 w1 = __ldg(&w2[2 * sub + 1]);

    cudaGridDependencySynchronize();   // AB (gemm output) ready after this

    uint4 ua[4], ub[4];
#pragma unroll
    for (int j = 0; j < 4; j++) ua[j] = __ldg(&g_ab[(size_t)hh[j] * 32 + sub]);
#pragma unroll
    for (int j = 0; j < 4; j++) ub[j] = __ldg(&g_ab[(size_t)tt[j] * 32 + 16 + sub]);

    float s[4];
#pragma unroll
    for (int j = 0; j < 4; j++) s[j] = edge_dot(ua[j], ub[j], ur[j], w0, w1);
#pragma unroll
    for (int m = 8; m >= 1; m >>= 1) {
#pragma unroll
        for (int j = 0; j < 4; j++) s[j] += __shfl_xor_sync(0xffffffff, s[j], m);
    }
    if (sub == 0) {
        float bb = __ldg(b2);
        if (!tail) {                     // full quad: coalesced float4 store
            *(float4*)(out + eb) = make_float4(s[0] + bb, s[1] + bb,
                                               s[2] + bb, s[3] + bb);
        } else {
#pragma unroll
            for (int j = 0; j < 4; j++)
                if (eb + j < E) out[eb + j] = s[j] + bb;
        }
    }
}

// ---------------------------------------------------------------------------
// Streams/events created in a static initializer (before harness checkpoints).
struct HxRes {
    cudaStream_t s1, s2;
    cudaEvent_t e0, e1, e2;
    HxRes() {
        cudaStreamCreateWithFlags(&s1, cudaStreamNonBlocking);
        cudaStreamCreateWithFlags(&s2, cudaStreamNonBlocking);
        cudaEventCreateWithFlags(&e0, cudaEventDisableTiming);
        cudaEventCreateWithFlags(&e1, cudaEventDisableTiming);
        cudaEventCreateWithFlags(&e2, cudaEventDisableTiming);
    }
};
static HxRes hx;

// Launch helper: kernel with Programmatic Stream Serialization (PDL secondary).
template <typename F, typename... Args>
static void launch_pdl(F f, dim3 grid, dim3 block, cudaStream_t st, Args... args) {
    cudaLaunchAttribute attr[1];
    attr[0].id = cudaLaunchAttributeProgrammaticStreamSerialization;
    attr[0].val.programmaticStreamSerializationAllowed = 1;
    cudaLaunchConfig_t cfg{};
    cfg.gridDim = grid;
    cfg.blockDim = block;
    cfg.dynamicSmemBytes = 0;
    cfg.stream = st;
    cfg.attrs = attr;
    cfg.numAttrs = 1;
    cudaLaunchKernelEx(&cfg, f, args...);
}

extern "C" void kernel_launch(void* const* d_in, const int* in_sizes, int n_in,
                              void* d_out, int out_size) {
    int off = (n_in >= 13) ? 0 : -1;   // robust to scalar input being dropped
    const void*  ph    = d_in[0];
    const void*  pr    = d_in[1];
    const void*  pt    = d_in[2];
    const float* q     = (const float*)d_in[3];
    const float* ent   = (const float*)d_in[4];
    const float* rel   = (const float*)d_in[6 + off];
    const float* topic = (const float*)d_in[7 + off];
    const float* nont  = (const float*)d_in[8 + off];
    const float* W1    = (const float*)d_in[9 + off];
    const float* b1    = (const float*)d_in[10 + off];
    const float* W2    = (const float*)d_in[11 + off];
    const float* b2    = (const float*)d_in[12 + off];

    int E     = in_sizes[0];
    int Ntext = in_sizes[4] / 128;
    int NREL  = in_sizes[6 + off] / 128;
    int Nn    = in_sizes[7 + off] / 2;
    if (E > E_MAX) E = E_MAX;
    if (Nn > N_MAX) Nn = N_MAX;
    if (NREL > 512) NREL = 512;

    int gE2 = ((E + 1) / 2 + 255) / 256;     // 2 edges per thread
    int nrelb = (NREL + 1) / 2;

    // fork: fill on s1, prep on s2, DDE chain on the main stream
    cudaEventRecord(hx.e0, 0);
    cudaStreamWaitEvent(hx.s1, hx.e0, 0);
    cudaStreamWaitEvent(hx.s2, hx.e0, 0);

    k_fill<<<(Nn * 32 + 255) / 256, 256, 0, hx.s1>>>(ent, nont, Nn, Ntext);
    cudaEventRecord(hx.e1, hx.s1);

    k_prep<<<144 + nrelb, 256, 0, hx.s2>>>(W1, rel, q, b1, NREL);
    cudaEventRecord(hx.e2, hx.s2);

    // PDL chain on the main stream (late triggers -> serial-equivalent data flow)
    k_convert<<<gE2, 256>>>(ph, pr, pt, topic, E);   // ids + DDE round 0 + counts
    launch_pdl(k_scat, dim3(gE2), dim3(256), (cudaStream_t)0, 1, E);
    launch_pdl(k_scat, dim3(gE2), dim3(256), (cudaStream_t)0, 2, E);

    // gemm needs fill (A), prep (Wcat) and the DDE chain
    cudaStreamWaitEvent(0, hx.e1, 0);
    cudaStreamWaitEvent(0, hx.e2, 0);
    launch_pdl(k_gemm, dim3((Nn + 127) / 128, 2), dim3(256), (cudaStream_t)0,
               topic, Nn);

    // edge: PDL secondary of gemm; 4 edges per 16-lane group -> E*4 threads
    launch_pdl(k_edge, dim3((E * 4 + 255) / 256), dim3(256), (cudaStream_t)0,
               (float*)d_out, (const float4*)W2, b2, E);
}

// round 17
// speedup vs baseline: 1.1815x; 1.0750x over previous
#include <cuda_runtime.h>
#include <cuda_bf16.h>
#include <cuda_fp16.h>

// ---------------------------------------------------------------------------
// Retriever: out[e] = relu([q | h_e[h] | r_emb[r] | h_e[t]] @ W1 + b1) @ W2 + b2
//   R'     = rel_embs @ W1[270:398] + (q @ W1[0:128] + b1)    (500 x 128, fp16)
//   AB     = h_e @ [W1[128:270] | W1[398:540]]                (N x 256, fp16)
//            single-product fp16 mma.sync GEMM (fp32 accum); DDE columns
//            synthesized into SMEM inside the GEMM (128x128 tile, gridY=2).
//   out[e] = W2 . relu(AB[h,0:128] + AB[t,128:256] + R'[r]) + b2
// NOTES: harness PTX targets plain sm_100 -> tcgen05 unavailable; mma.sync only.
//        R9: DDE kernels are LSU/LTS-throughput bound.
//        R10: 128x256 GEMM tile regressed (mma-issue bound) -> 128x128 kept.
//        R12: griddepsync waits only for the TRIGGER; early triggers race.
//        R13: late triggers everywhere -> serial-equivalent PDL chain.
//        R7+R14: GEMM/DDE overlap net-NEGATIVE. Serial is final.
//        R16: ids packed into ONE uint64 (h|t<<17|r<<34).
//        R17: GEMM 3-buffer cp.async rotation -> ONE __syncthreads per
//        k-iteration (trailing barrier provably redundant with 3 bufs).
// ---------------------------------------------------------------------------

#define E_MAX 500000
#define N_MAX 100000
#define HE_W  144      // row pitch in fp16 for h_e / Wcat (142 used, 2 zero)

__device__ unsigned long long g_pk[E_MAX];             // packed h|t<<17|r<<34
__device__ float4 g_f0[N_MAX];                         // fwd r1 sums + cnt_t in .z
__device__ float4 g_r0[N_MAX];                         // rev r1 sums + cnt_h in .z
__device__ float2 g_f1[N_MAX], g_f2[N_MAX];            // fwd rounds 2,3 sums
__device__ float2 g_r1[N_MAX], g_r2[N_MAX];            // rev rounds 2,3 sums
__device__ __half g_hef[(size_t)N_MAX * HE_W];         // h_e fp16 (cols 0..127)
__device__ __half g_wf[256 * HE_W];                    // Wcat fp16, [n][k]
__device__ uint4  g_ab[(size_t)N_MAX * 32];            // AB  [N,256] fp16
__device__ uint4  g_rp[512 * 16];                      // R' [NREL,128] fp16

__device__ __forceinline__ unsigned long long packid(int h, int t, int r) {
    return (unsigned long long)(unsigned)h
         | ((unsigned long long)(unsigned)t << 17)
         | ((unsigned long long)(unsigned)r << 34);
}
#define UNPK_H(p) ((int)((p) & 0x1FFFFULL))
#define UNPK_T(p) ((int)(((p) >> 17) & 0x1FFFFULL))
#define UNPK_R(p) ((int)(((p) >> 34) & 0x3FFULL))

__device__ __forceinline__ unsigned packh2(float x, float y) {
    __half2 t = __floats2half2_rn(x, y);
    return *(unsigned*)&t;
}
__device__ __forceinline__ float2 h22f(unsigned u) {
    return __half22float2(*(__half2*)&u);
}
__device__ __forceinline__ void red2(float2* p, float x, float y) {
    asm volatile("red.global.add.v2.f32 [%0], {%1, %2};"
                 :: "l"(p), "f"(x), "f"(y) : "memory");
}
__device__ __forceinline__ void red4(float4* p, float x, float y, float z, float w) {
    asm volatile("red.global.add.v4.f32 [%0], {%1, %2, %3, %4};"
                 :: "l"(p), "f"(x), "f"(y), "f"(z), "f"(w) : "memory");
}

// ---------------- build h_e fp16 cols 0..127 + zero DDE state ----------------
__global__ void k_fill(const float* __restrict__ ent, const float* __restrict__ nont,
                       int Nn, int Ntext) {
    int i = blockIdx.x * 256 + threadIdx.x;
    if (i >= Nn * 32) return;
    int node = i >> 5, c4 = i & 31;
    const float* src = (node < Ntext) ? (ent + (size_t)node * 128 + c4 * 4)
                                      : (nont + c4 * 4);
    float4 v = *(const float4*)src;
    *(uint2*)(g_hef + (size_t)node * HE_W + c4 * 4) =
        make_uint2(packh2(v.x, v.y), packh2(v.z, v.w));
    if (c4 == 0) {   // piggyback: zero DDE accumulators
        g_f0[node] = make_float4(0.f, 0.f, 0.f, 0.f);
        g_r0[node] = make_float4(0.f, 0.f, 0.f, 0.f);
        g_f1[node] = make_float2(0.f, 0.f);
        g_f2[node] = make_float2(0.f, 0.f);
        g_r1[node] = make_float2(0.f, 0.f);
        g_r2[node] = make_float2(0.f, 0.f);
    }
}

// ------- ids -> packed uint64 (+dtype detect) + DDE round 0; 2 edges/thread ---
// PDL primary: trigger at the END (after all writes).
__global__ void k_convert(const void* ph, const void* pr, const void* pt,
                          const float* __restrict__ topic, int E) {
    __shared__ int s64;
    if (threadIdx.x == 0) {
        // int64 vs int32: int64 view of int32 r-id buffer is >= 2^32 a.s.
        const long long* p = (const long long*)ph;
        const long long* qq = (const long long*)pr;
        int ok = 1;
        for (int i = 0; i < 8; i++) {
            long long v = p[i];  if (v < 0 || v >= 1000000) ok = 0;
            long long w = qq[i]; if (w < 0 || w >= 1000000) ok = 0;
        }
        s64 = ok;
    }
    __syncthreads();
    int base = (blockIdx.x * 256 + threadIdx.x) * 2;
    if (base < E) {
        bool full = (base + 1 < E);
        int h[2], r[2], t[2];
        if (s64) {
            if (full) {
                longlong2 lh = __ldg((const longlong2*)ph + (base >> 1));
                longlong2 lr = __ldg((const longlong2*)pr + (base >> 1));
                longlong2 lt = __ldg((const longlong2*)pt + (base >> 1));
                h[0] = (int)lh.x; h[1] = (int)lh.y;
                r[0] = (int)lr.x; r[1] = (int)lr.y;
                t[0] = (int)lt.x; t[1] = (int)lt.y;
            } else {
                h[0] = h[1] = (int)((const long long*)ph)[base];
                r[0] = r[1] = (int)((const long long*)pr)[base];
                t[0] = t[1] = (int)((const long long*)pt)[base];
            }
        } else {
            if (full) {
                int2 ih = __ldg((const int2*)ph + (base >> 1));
                int2 ir = __ldg((const int2*)pr + (base >> 1));
                int2 it = __ldg((const int2*)pt + (base >> 1));
                h[0] = ih.x; h[1] = ih.y;
                r[0] = ir.x; r[1] = ir.y;
                t[0] = it.x; t[1] = it.y;
            } else {
                h[0] = h[1] = ((const int*)ph)[base];
                r[0] = r[1] = ((const int*)pr)[base];
                t[0] = t[1] = ((const int*)pt)[base];
            }
        }
        const float2* tp2 = (const float2*)topic;
        float2 th0 = __ldg(tp2 + h[0]);
        float2 tt0 = __ldg(tp2 + t[0]);
        float2 th1 = __ldg(tp2 + h[1]);
        float2 tt1 = __ldg(tp2 + t[1]);
        if (full) {
            *(longlong2*)(g_pk + base) = make_longlong2(
                (long long)packid(h[0], t[0], r[0]),
                (long long)packid(h[1], t[1], r[1]));
        } else {
            g_pk[base] = packid(h[0], t[0], r[0]);
        }
        red4(&g_f0[t[0]], th0.x, th0.y, 1.0f, 0.f);
        red4(&g_r0[h[0]], tt0.x, tt0.y, 1.0f, 0.f);
        if (full) {
            red4(&g_f0[t[1]], th1.x, th1.y, 1.0f, 0.f);
            red4(&g_r0[h[1]], tt1.x, tt1.y, 1.0f, 0.f);
        }
    }
    cudaTriggerProgrammaticLaunchCompletion();   // AFTER all work (R12 lesson)
}

// ------- DDE scatter round rd (1 or 2); 2 edges per thread --------------------
// PDL secondary + primary: griddepsync at top, trigger at END.
__global__ void k_scat(int rd, int E) {
    cudaGridDependencySynchronize();
    int base = (blockIdx.x * 256 + threadIdx.x) * 2;
    if (base < E) {
        bool full = (base + 1 < E);
        unsigned long long p0, p1;
        if (full) {
            longlong2 lp = __ldg((const longlong2*)(g_pk + base));
            p0 = (unsigned long long)lp.x;
            p1 = (unsigned long long)lp.y;
        } else {
            p0 = p1 = g_pk[base];
        }
        int h0 = UNPK_H(p0), t0 = UNPK_T(p0);
        int h1 = UNPK_H(p1), t1 = UNPK_T(p1);
        if (rd == 1) {
            float4 f0h0 = __ldg(&g_f0[h0]);
            float4 r0t0 = __ldg(&g_r0[t0]);
            float4 f0h1 = __ldg(&g_f0[h1]);
            float4 r0t1 = __ldg(&g_r0[t1]);
            float ia = 1.0f / fmaxf(f0h0.z, 1.0f);
            float ib = 1.0f / fmaxf(r0t0.z, 1.0f);
            float ic = 1.0f / fmaxf(f0h1.z, 1.0f);
            float id = 1.0f / fmaxf(r0t1.z, 1.0f);
            red2(&g_f1[t0], f0h0.x * ia, f0h0.y * ia);
            red2(&g_r1[h0], r0t0.x * ib, r0t0.y * ib);
            if (full) {
                red2(&g_f1[t1], f0h1.x * ic, f0h1.y * ic);
                red2(&g_r1[h1], r0t1.x * id, r0t1.y * id);
            }
        } else {
            const float* cb = (const float*)g_f0;
            const float* ch = (const float*)g_r0;
            float ca0 = __ldg(cb + 4 * (size_t)h0 + 2);
            float cb0 = __ldg(ch + 4 * (size_t)t0 + 2);
            float ca1 = __ldg(cb + 4 * (size_t)h1 + 2);
            float cb1 = __ldg(ch + 4 * (size_t)t1 + 2);
            float2 f1h0 = __ldg(&g_f1[h0]);
            float2 r1t0 = __ldg(&g_r1[t0]);
            float2 f1h1 = __ldg(&g_f1[h1]);
            float2 r1t1 = __ldg(&g_r1[t1]);
            float ia = 1.0f / fmaxf(ca0, 1.0f);
            float ib = 1.0f / fmaxf(cb0, 1.0f);
            float ic = 1.0f / fmaxf(ca1, 1.0f);
            float id = 1.0f / fmaxf(cb1, 1.0f);
            red2(&g_f2[t0], f1h0.x * ia, f1h0.y * ia);
            red2(&g_r2[h0], r1t0.x * ib, r1t0.y * ib);
            if (full) {
                red2(&g_f2[t1], f1h1.x * ic, f1h1.y * ic);
                red2(&g_r2[h1], r1t1.x * id, r1t1.y * id);
            }
        }
    }
    cudaTriggerProgrammaticLaunchCompletion();   // AFTER all work
}

// ------- prep: Wcat fp16 [n][k] | R' = rel@W1_r + (q@W1_q + b1), fp16 ----------
__global__ void k_prep(const float* __restrict__ W1, const float* __restrict__ rel,
                       const float* __restrict__ q, const float* __restrict__ b1,
                       int NREL) {
    int bid = blockIdx.x;
    int tid = threadIdx.x;
    if (bid < 144) {                       // Wcat: 256 elements of the [n][k] array
        int idx = bid * 256 + tid;
        int n = idx / 144, k = idx % 144;
        float v = 0.f;
        if (k < 142) v = (n < 128) ? W1[(128 + k) * 128 + n]
                                   : W1[(398 + k) * 128 + (n - 128)];
        g_wf[idx] = __float2half(v);
    } else {                               // two relations per block
        __shared__ float rs[256];
        __shared__ float qs[128];
        int r = (bid - 144) * 2 + (tid >> 7);
        int j = tid & 127;
        int base = tid & ~127;
        if (tid < 128) qs[tid] = q[tid];
        rs[tid] = (r < NREL) ? rel[(size_t)r * 128 + j] : 0.f;
        __syncthreads();
        if (r < NREL) {
            float accc = b1[j];
#pragma unroll 8
            for (int k = 0; k < 128; k++) accc += qs[k] * __ldg(&W1[k * 128 + j]);
            float accr = 0.f;
#pragma unroll 8
            for (int k = 0; k < 128; k++) accr += rs[base + k] * __ldg(&W1[(270 + k) * 128 + j]);
            ((__half*)g_rp)[(size_t)r * 128 + j] = __float2half(accc + accr);
        }
    }
}

// ---------------------------------------------------------------------------
// GEMM: AB[N,256] = h_e[N,144] @ Wcat[144,256], single-product fp16 mma.sync,
// fp32 accum. Block 128x128 (gridY = n-half), 8 warps (2x4), warp tile 64x32,
// BK=16. THREE rotating cp.async buffers (tile s -> buf s%3), depth-2
// pipeline -> ONE __syncthreads per iteration: staging tile it+2 writes buf
// (it-1)%3 whose readers all passed this iteration's barrier.
// PDL: griddepsync before the DDE tile-8 synthesis; trigger at the very END.
// ---------------------------------------------------------------------------
#define APITCH 24   // smem row pitch in fp16 (48B -> conflict-free ldmatrix)
#define R_EL   (128 * APITCH)   // elements per region (3072)

__device__ __forceinline__ void ldsm4(unsigned* r, unsigned a) {
    asm volatile("ldmatrix.sync.aligned.m8n8.x4.shared.b16 {%0,%1,%2,%3}, [%4];"
                 : "=r"(r[0]), "=r"(r[1]), "=r"(r[2]), "=r"(r[3]) : "r"(a));
}
__device__ __forceinline__ void mma_f16(float* d, const unsigned* a, unsigned b0, unsigned b1) {
    asm volatile("mma.sync.aligned.m16n8k16.row.col.f32.f16.f16.f32 "
                 "{%0,%1,%2,%3}, {%4,%5,%6,%7}, {%8,%9}, {%0,%1,%2,%3};"
                 : "+f"(d[0]), "+f"(d[1]), "+f"(d[2]), "+f"(d[3])
                 : "r"(a[0]), "r"(a[1]), "r"(a[2]), "r"(a[3]), "r"(b0), "r"(b1));
}
__device__ __forceinline__ void cp16(unsigned dst, const void* src) {
    asm volatile("cp.async.ca.shared.global [%0], [%1], 16;" :: "r"(dst), "l"(src));
}

__global__ __launch_bounds__(256) void k_gemm(const float* __restrict__ topic, int Nn) {
    // smem (fp16 el): A bufs 0..2 at [0,3R); B bufs 0..2 at [3R,6R)  (36 KB)
    __shared__ __align__(16) __half sm[6 * R_EL];
    unsigned smb = (unsigned)__cvta_generic_to_shared(sm);
    int tid = threadIdx.x;
    int m0 = blockIdx.x * 128, n0 = blockIdx.y * 128;
    int wid = tid >> 5, lane = tid & 31;
    int wm = (wid >> 2) * 64, wn = (wid & 3) * 32;

    // staging: slot 0 = A, slot 1 = B; per tile each thread copies one 16B unit.
    int row = tid >> 1, half = tid & 1;                // 128 rows x 2 halves
    const __half* gbA;
    const __half* gbB;
    unsigned dstA, dstB;                               // bytes, excluding buf
    {
        int gr = m0 + row; if (gr >= Nn) gr = Nn - 1;
        gbA = g_hef + (size_t)gr * HE_W + half * 8;
        gbB = g_wf + (size_t)(n0 + row) * HE_W + half * 8;
        dstA = (unsigned)(row * APITCH + half * 8) * 2;
        dstB = (unsigned)(3 * R_EL + row * APITCH + half * 8) * 2;
    }
    const unsigned strR = R_EL * 2;                    // bytes per buffer region

    float acc[4][4][4];
#pragma unroll
    for (int i = 0; i < 4; i++)
#pragma unroll
        for (int j = 0; j < 4; j++)
#pragma unroll
            for (int k = 0; k < 4; k++) acc[i][j][k] = 0.f;

    int ldrow = lane & 15, ldk = (lane >> 4) * 8;

    // ---- prologue: stage tiles 0 and 1 as separate groups ----
    cp16(smb + dstA, gbA);
    cp16(smb + dstB, gbB);
    asm volatile("cp.async.commit_group;");
    cp16(smb + strR + dstA, gbA + 16);
    cp16(smb + strR + dstB, gbB + 16);
    asm volatile("cp.async.commit_group;");

#pragma unroll
    for (int it = 0; it <= 8; ++it) {
        if (it < 8) asm volatile("cp.async.wait_group 1;");
        else        asm volatile("cp.async.wait_group 0;");
        __syncthreads();   // tile it visible; all reads of buf (it-1)%3 done

        int s = it + 2;
        if (s <= 8) {
            unsigned bofs = (unsigned)(s % 3) * strR;
            if (s < 8) {
                cp16(smb + bofs + dstA, gbA + s * 16);
                cp16(smb + bofs + dstB, gbB + s * 16);
            } else {
                // tile 8 needs scat2's DDE output: full dependency sync first.
                cudaGridDependencySynchronize();
                // B via cp.async (Wcat cols 128..143), A synthesized
                cp16(smb + bofs + dstB, gbB + 8 * 16);
                int i = m0 + row; if (i >= Nn) i = Nn - 1;
                float v[8];
                if (half == 0) {  // cols 128..135: topic, fwd rounds 1..3
                    float2 tp = __ldg(((const float2*)topic) + i);
                    float4 f0 = g_f0[i];
                    float2 f1 = g_f1[i], f2 = g_f2[i];
                    float ict = 1.0f / fmaxf(f0.z, 1.0f);
                    v[0] = tp.x;       v[1] = tp.y;
                    v[2] = f0.x * ict; v[3] = f0.y * ict;
                    v[4] = f1.x * ict; v[5] = f1.y * ict;
                    v[6] = f2.x * ict; v[7] = f2.y * ict;
                } else {          // cols 136..143: rev rounds 1..3, pad
                    float4 r0 = g_r0[i];
                    float2 r1 = g_r1[i], r2 = g_r2[i];
                    float ich = 1.0f / fmaxf(r0.z, 1.0f);
                    v[0] = r0.x * ich; v[1] = r0.y * ich;
                    v[2] = r1.x * ich; v[3] = r1.y * ich;
                    v[4] = r2.x * ich; v[5] = r2.y * ich;
                    v[6] = 0.f;        v[7] = 0.f;
                }
                *(uint4*)((char*)sm + bofs + dstA) =
                    make_uint4(packh2(v[0], v[1]), packh2(v[2], v[3]),
                               packh2(v[4], v[5]), packh2(v[6], v[7]));
            }
            asm volatile("cp.async.commit_group;");
        } else {
            // keep group accounting uniform (empty group)
            asm volatile("cp.async.commit_group;");
        }

        // ---- fragments from buf it%3 ----
        unsigned aoff = (unsigned)(it % 3) * strR;
        unsigned boff = 3 * strR + aoff;
        unsigned Af[4][4], Bf[2][4];
#pragma unroll
        for (int mf = 0; mf < 4; mf++) {
            unsigned r = (wm + mf * 16 + ldrow) * APITCH + ldk;
            ldsm4(Af[mf], smb + aoff + r * 2);
        }
#pragma unroll
        for (int nh = 0; nh < 2; nh++) {
            unsigned r = (wn + nh * 16 + ldrow) * APITCH + ldk;
            ldsm4(Bf[nh], smb + boff + r * 2);
        }
#pragma unroll
        for (int mf = 0; mf < 4; mf++)
#pragma unroll
            for (int nf = 0; nf < 4; nf++) {
                int nh = nf >> 1, sel = nf & 1;
                mma_f16(acc[mf][nf], Af[mf], Bf[nh][sel], Bf[nh][sel + 2]);
            }
    }

    // ---- epilogue: fp32 acc -> fp16 AB ----
    int g = lane >> 2, tg = lane & 3;
    unsigned* outw = (unsigned*)g_ab;
#pragma unroll
    for (int mf = 0; mf < 4; mf++)
#pragma unroll
        for (int nf = 0; nf < 4; nf++) {
            int col = n0 + wn + nf * 8 + 2 * tg;
            int r0 = m0 + wm + mf * 16 + g;
            if (r0 < Nn)
                outw[(size_t)r0 * 128 + (col >> 1)] = packh2(acc[mf][nf][0], acc[mf][nf][1]);
            int r1 = r0 + 8;
            if (r1 < Nn)
                outw[(size_t)r1 * 128 + (col >> 1)] = packh2(acc[mf][nf][2], acc[mf][nf][3]);
        }
    cudaTriggerProgrammaticLaunchCompletion();   // AFTER epilogue stores
}

// -------- edge stage: 4 edges per 16-lane group, 12 batched uint4 gathers -----
// PDL secondary of gemm: packed ids / R' / W2 loaded BEFORE griddepsync,
// overlapping gemm's drain; AB gathers after.
__device__ __forceinline__ float edge_dot(uint4 ua, uint4 ub, uint4 ur,
                                          float4 w0, float4 w1) {
    float2 a0 = h22f(ua.x), a1 = h22f(ua.y), a2 = h22f(ua.z), a3 = h22f(ua.w);
    float2 b0 = h22f(ub.x), b1 = h22f(ub.y), b2 = h22f(ub.z), b3 = h22f(ub.w);
    float2 c0 = h22f(ur.x), c1 = h22f(ur.y), c2 = h22f(ur.z), c3 = h22f(ur.w);
    return fmaxf(a0.x + b0.x + c0.x, 0.f) * w0.x
         + fmaxf(a0.y + b0.y + c0.y, 0.f) * w0.y
         + fmaxf(a1.x + b1.x + c1.x, 0.f) * w0.z
         + fmaxf(a1.y + b1.y + c1.y, 0.f) * w0.w
         + fmaxf(a2.x + b2.x + c2.x, 0.f) * w1.x
         + fmaxf(a2.y + b2.y + c2.y, 0.f) * w1.y
         + fmaxf(a3.x + b3.x + c3.x, 0.f) * w1.z
         + fmaxf(a3.y + b3.y + c3.y, 0.f) * w1.w;
}

__global__ __launch_bounds__(256) void k_edge(float* __restrict__ out,
                                              const float4* __restrict__ w2,
                                              const float* __restrict__ b2, int E) {
    int gt = blockIdx.x * 256 + threadIdx.x;
    int quad = gt >> 4, sub = gt & 15;
    int eb = quad * 4;
    if (eb >= E) { cudaGridDependencySynchronize(); return; }
    bool tail = (eb + 3 >= E);
    unsigned long long pk[4];
    if (!tail) {     // eb multiple of 4 -> 32B-aligned longlong2 pair
        longlong2 l0 = __ldg((const longlong2*)(g_pk + eb));
        longlong2 l1 = __ldg((const longlong2*)(g_pk + eb + 2));
        pk[0] = (unsigned long long)l0.x; pk[1] = (unsigned long long)l0.y;
        pk[2] = (unsigned long long)l1.x; pk[3] = (unsigned long long)l1.y;
    } else {
#pragma unroll
        for (int j = 0; j < 4; j++) {
            int e = (eb + j < E) ? eb + j : E - 1;
            pk[j] = g_pk[e];
        }
    }
    int hh[4], tt[4], rr[4];
#pragma unroll
    for (int j = 0; j < 4; j++) {
        hh[j] = UNPK_H(pk[j]); tt[j] = UNPK_T(pk[j]); rr[j] = UNPK_R(pk[j]);
    }
    // pre-sync: R' gathers + W2 (complete before gemm launched)
    uint4 ur[4];
#pragma unroll
    for (int j = 0; j < 4; j++) ur[j] = __ldg(&g_rp[(size_t)rr[j] * 16 + sub]);
    float4 w0 = __ldg(&w2[2 * sub]);
    float4 w1 = __ldg(&w2[2 * sub + 1]);

    cudaGridDependencySynchronize();   // AB (gemm output) ready after this

    uint4 ua[4], ub[4];
#pragma unroll
    for (int j = 0; j < 4; j++) ua[j] = __ldg(&g_ab[(size_t)hh[j] * 32 + sub]);
#pragma unroll
    for (int j = 0; j < 4; j++) ub[j] = __ldg(&g_ab[(size_t)tt[j] * 32 + 16 + sub]);

    float s[4];
#pragma unroll
    for (int j = 0; j < 4; j++) s[j] = edge_dot(ua[j], ub[j], ur[j], w0, w1);
#pragma unroll
    for (int m = 8; m >= 1; m >>= 1) {
#pragma unroll
        for (int j = 0; j < 4; j++) s[j] += __shfl_xor_sync(0xffffffff, s[j], m);
    }
    if (sub == 0) {
        float bb = __ldg(b2);
        if (!tail) {                     // full quad: coalesced float4 store
            *(float4*)(out + eb) = make_float4(s[0] + bb, s[1] + bb,
                                               s[2] + bb, s[3] + bb);
        } else {
#pragma unroll
            for (int j = 0; j < 4; j++)
                if (eb + j < E) out[eb + j] = s[j] + bb;
        }
    }
}

// ---------------------------------------------------------------------------
// Streams/events created in a static initializer (before harness checkpoints).
struct HxRes {
    cudaStream_t s1, s2;
    cudaEvent_t e0, e1, e2;
    HxRes() {
        cudaStreamCreateWithFlags(&s1, cudaStreamNonBlocking);
        cudaStreamCreateWithFlags(&s2, cudaStreamNonBlocking);
        cudaEventCreateWithFlags(&e0, cudaEventDisableTiming);
        cudaEventCreateWithFlags(&e1, cudaEventDisableTiming);
        cudaEventCreateWithFlags(&e2, cudaEventDisableTiming);
    }
};
static HxRes hx;

// Launch helper: kernel with Programmatic Stream Serialization (PDL secondary).
template <typename F, typename... Args>
static void launch_pdl(F f, dim3 grid, dim3 block, cudaStream_t st, Args... args) {
    cudaLaunchAttribute attr[1];
    attr[0].id = cudaLaunchAttributeProgrammaticStreamSerialization;
    attr[0].val.programmaticStreamSerializationAllowed = 1;
    cudaLaunchConfig_t cfg{};
    cfg.gridDim = grid;
    cfg.blockDim = block;
    cfg.dynamicSmemBytes = 0;
    cfg.stream = st;
    cfg.attrs = attr;
    cfg.numAttrs = 1;
    cudaLaunchKernelEx(&cfg, f, args...);
}

extern "C" void kernel_launch(void* const* d_in, const int* in_sizes, int n_in,
                              void* d_out, int out_size) {
    int off = (n_in >= 13) ? 0 : -1;   // robust to scalar input being dropped
    const void*  ph    = d_in[0];
    const void*  pr    = d_in[1];
    const void*  pt    = d_in[2];
    const float* q     = (const float*)d_in[3];
    const float* ent   = (const float*)d_in[4];
    const float* rel   = (const float*)d_in[6 + off];
    const float* topic = (const float*)d_in[7 + off];
    const float* nont  = (const float*)d_in[8 + off];
    const float* W1    = (const float*)d_in[9 + off];
    const float* b1    = (const float*)d_in[10 + off];
    const float* W2    = (const float*)d_in[11 + off];
    const float* b2    = (const float*)d_in[12 + off];

    int E     = in_sizes[0];
    int Ntext = in_sizes[4] / 128;
    int NREL  = in_sizes[6 + off] / 128;
    int Nn    = in_sizes[7 + off] / 2;
    if (E > E_MAX) E = E_MAX;
    if (Nn > N_MAX) Nn = N_MAX;
    if (NREL > 512) NREL = 512;

    int gE2 = ((E + 1) / 2 + 255) / 256;     // 2 edges per thread
    int nrelb = (NREL + 1) / 2;

    // fork: fill on s1, prep on s2, DDE chain on the main stream
    cudaEventRecord(hx.e0, 0);
    cudaStreamWaitEvent(hx.s1, hx.e0, 0);
    cudaStreamWaitEvent(hx.s2, hx.e0, 0);

    k_fill<<<(Nn * 32 + 255) / 256, 256, 0, hx.s1>>>(ent, nont, Nn, Ntext);
    cudaEventRecord(hx.e1, hx.s1);

    k_prep<<<144 + nrelb, 256, 0, hx.s2>>>(W1, rel, q, b1, NREL);
    cudaEventRecord(hx.e2, hx.s2);

    // PDL chain on the main stream (late triggers -> serial-equivalent data flow)
    k_convert<<<gE2, 256>>>(ph, pr, pt, topic, E);   // ids + DDE round 0 + counts
    launch_pdl(k_scat, dim3(gE2), dim3(256), (cudaStream_t)0, 1, E);
    launch_pdl(k_scat, dim3(gE2), dim3(256), (cudaStream_t)0, 2, E);

    // gemm needs fill (A), prep (Wcat) and the DDE chain
    cudaStreamWaitEvent(0, hx.e1, 0);
    cudaStreamWaitEvent(0, hx.e2, 0);
    launch_pdl(k_gemm, dim3((Nn + 127) / 128, 2), dim3(256), (cudaStream_t)0,
               topic, Nn);

    // edge: PDL secondary of gemm; 4 edges per 16-lane group -> E*4 threads
    launch_pdl(k_edge, dim3((E * 4 + 255) / 256), dim3(256), (cudaStream_t)0,
               (float*)d_out, (const float4*)W2, b2, E);
}